// round 13
// baseline (speedup 1.0000x reference)
#include <cuda_runtime.h>
#include <cuda_fp16.h>
#include <math.h>
#include <stdint.h>

// ---------------- problem constants ----------------
#define N_NODES 6000
#define JP      6016           // N padded to multiple of 64
#define F_IN    512
#define HID     64
#define H1      8
#define C_OUT   40
#define NW      188
#define ALPHA   0.2f
#define OUT_ADJ_OFF (N_NODES * C_OUT)
#define NT_FULL 94             // JP/64
#define G1_BLOCKS (47 * H1)    // gemm1 blocks inside fused kernel
#define PACK_BLOCKS ((N_NODES * NW) / 8)   // 141000 blocks of 8 warps

// ---------------- device scratch ----------------
__device__ float    g_Wh  [H1 * N_NODES * HID];
__device__ __half   g_WhT [H1 * HID * (size_t)JP];
__device__ unsigned g_adjb[N_NODES * NW];
__device__ float    g_h1  [N_NODES * (H1 * HID)];
__device__ float    g_Wh2 [N_NODES * C_OUT];
__device__ __half   g_WhT2[HID * (size_t)JP];
__device__ float    g_part[24 * 6016 * 72];      // partials: stride 72; L1 Z@64, L2 Z@40

__device__ float  g_Ei[H1 * N_NODES], g_Fi[H1 * N_NODES];
__device__ float  g_E2i[N_NODES], g_F2i[N_NODES];
// packed per-j tables: entry (j/2) = { e2, f2 } halves; zero in pad region
__device__ uint2  g_pk1[H1 * (JP / 2)];
__device__ uint2  g_pk2[JP / 2];

// ---------------- helpers ----------------
__device__ __forceinline__ uint32_t smem_u32(const void* p) {
    uint32_t a;
    asm("{ .reg .u64 t; cvta.to.shared.u64 t, %1; cvt.u32.u64 %0, t; }" : "=r"(a) : "l"(p));
    return a;
}
__device__ __forceinline__ void mma_16816(float c[4], const uint32_t a[4], const uint32_t b[2]) {
    asm volatile(
        "mma.sync.aligned.m16n8k16.row.col.f32.f16.f16.f32 "
        "{%0,%1,%2,%3}, {%4,%5,%6,%7}, {%8,%9}, {%0,%1,%2,%3};"
        : "+f"(c[0]), "+f"(c[1]), "+f"(c[2]), "+f"(c[3])
        : "r"(a[0]), "r"(a[1]), "r"(a[2]), "r"(a[3]), "r"(b[0]), "r"(b[1]));
}
__device__ __forceinline__ void mma_tf32(float c[4], const uint32_t a[4], const uint32_t b[2]) {
    asm volatile(
        "mma.sync.aligned.m16n8k8.row.col.f32.tf32.tf32.f32 "
        "{%0,%1,%2,%3}, {%4,%5,%6,%7}, {%8,%9}, {%0,%1,%2,%3};"
        : "+f"(c[0]), "+f"(c[1]), "+f"(c[2]), "+f"(c[3])
        : "r"(a[0]), "r"(a[1]), "r"(a[2]), "r"(a[3]), "r"(b[0]), "r"(b[1]));
}
__device__ __forceinline__ void ldsm_x4(uint32_t& r0, uint32_t& r1, uint32_t& r2, uint32_t& r3,
                                        uint32_t addr) {
    asm volatile("ldmatrix.sync.aligned.m8n8.x4.shared.b16 {%0,%1,%2,%3}, [%4];"
                 : "=r"(r0), "=r"(r1), "=r"(r2), "=r"(r3) : "r"(addr));
}
__device__ __forceinline__ uint32_t tf32_of(float x) {
    uint32_t r;
    asm("cvt.rna.tf32.f32 %0, %1;" : "=r"(r) : "f"(x));
    return r;
}
#define CP_ASYNC16(dst, src) \
    asm volatile("cp.async.cg.shared.global [%0], [%1], 16;" :: "r"(dst), "l"(src))
#define CP_COMMIT() asm volatile("cp.async.commit_group;" ::: "memory")
#define CP_WAIT1()  asm volatile("cp.async.wait_group 1;" ::: "memory")
#define CP_WAIT0()  asm volatile("cp.async.wait_group 0;" ::: "memory")

// ---------------- tf32 GEMM template body (256 threads) ----------------
template<int NB>
__device__ __forceinline__ void gemm_tf32_body(
    const float* __restrict__ Asrc,
    const float* __restrict__ Bsrc,
    float* __restrict__ Cout,
    __half* __restrict__ CtT,
    int i0)
{
    __shared__ __align__(16) char sbuf[17408];
    float* As = (float*)sbuf;                 // [128][20]
    float* Bs = (float*)(sbuf + 10240);       // [16][72]
    __half* T = (__half*)sbuf;                // [64][136] reused after mainloop

    int tid = threadIdx.x;
    int lane = tid & 31, warp = tid >> 5;
    int wr = warp >> 1, wc = warp & 1;

    float acc[2][4][4];
    #pragma unroll
    for (int m = 0; m < 2; m++)
        #pragma unroll
        for (int n = 0; n < 4; n++)
            #pragma unroll
            for (int c = 0; c < 4; c++) acc[m][n][c] = 0.f;

    int sr = tid >> 1, skk = (tid & 1) * 8;
    int bkk = tid >> 4, bn0 = (tid & 15) * 4;

    for (int k0 = 0; k0 < F_IN; k0 += 16) {
        {
            float4 v0 = make_float4(0.f, 0.f, 0.f, 0.f), v1 = v0;
            if (i0 + sr < N_NODES) {
                const float* src = &Asrc[(size_t)(i0 + sr) * F_IN + k0 + skk];
                v0 = *(const float4*)src;
                v1 = *(const float4*)(src + 4);
            }
            uint32_t* d = (uint32_t*)&As[sr * 20 + skk];
            d[0] = tf32_of(v0.x); d[1] = tf32_of(v0.y); d[2] = tf32_of(v0.z); d[3] = tf32_of(v0.w);
            d[4] = tf32_of(v1.x); d[5] = tf32_of(v1.y); d[6] = tf32_of(v1.z); d[7] = tf32_of(v1.w);
        }
        {
            float4 b = make_float4(0.f, 0.f, 0.f, 0.f);
            if (bn0 < NB)
                b = *(const float4*)&Bsrc[(size_t)(k0 + bkk) * NB + bn0];
            uint32_t* d = (uint32_t*)&Bs[bkk * 72 + bn0];
            d[0] = tf32_of(b.x); d[1] = tf32_of(b.y); d[2] = tf32_of(b.z); d[3] = tf32_of(b.w);
        }
        __syncthreads();

        #pragma unroll
        for (int s = 0; s < 2; s++) {
            int arow = wr * 32 + (lane >> 2);
            int akol = s * 8 + (lane & 3);
            uint32_t af[2][4];
            #pragma unroll
            for (int m = 0; m < 2; m++) {
                int base = (arow + m * 16) * 20 + akol;
                af[m][0] = __float_as_uint(As[base]);
                af[m][1] = __float_as_uint(As[base + 8 * 20]);
                af[m][2] = __float_as_uint(As[base + 4]);
                af[m][3] = __float_as_uint(As[base + 8 * 20 + 4]);
            }
            int bb = (s * 8 + (lane & 3)) * 72 + wc * 32 + (lane >> 2);
            uint32_t bf[4][2];
            #pragma unroll
            for (int n = 0; n < 4; n++) {
                bf[n][0] = __float_as_uint(Bs[bb + n * 8]);
                bf[n][1] = __float_as_uint(Bs[bb + n * 8 + 4 * 72]);
            }
            #pragma unroll
            for (int m = 0; m < 2; m++)
                #pragma unroll
                for (int n = 0; n < 4; n++)
                    mma_tf32(acc[m][n], af[m], bf[n]);
        }
        __syncthreads();
    }

    int rl = wr * 32 + (lane >> 2);
    int cbx = wc * 32 + (lane & 3) * 2;
    #pragma unroll
    for (int m = 0; m < 2; m++) {
        int r0 = rl + m * 16, r1 = r0 + 8;
        #pragma unroll
        for (int n = 0; n < 4; n++) {
            int c = cbx + n * 8;
            if (c < NB) {
                if (i0 + r0 < N_NODES)
                    *(float2*)&Cout[(size_t)(i0 + r0) * NB + c] =
                        make_float2(acc[m][n][0], acc[m][n][1]);
                if (i0 + r1 < N_NODES)
                    *(float2*)&Cout[(size_t)(i0 + r1) * NB + c] =
                        make_float2(acc[m][n][2], acc[m][n][3]);
            }
            T[(c + 0) * 136 + r0] = __float2half_rn(acc[m][n][0]);
            T[(c + 1) * 136 + r0] = __float2half_rn(acc[m][n][1]);
            T[(c + 0) * 136 + r1] = __float2half_rn(acc[m][n][2]);
            T[(c + 1) * 136 + r1] = __float2half_rn(acc[m][n][3]);
        }
    }
    __syncthreads();
    #pragma unroll
    for (int q = 0; q < 4; q++) {
        int l = tid + 256 * q;               // 0..1023
        int d = l >> 4, o = (l & 15) * 8;
        *(uint4*)&CtT[(size_t)d * JP + i0 + o] = *(uint4*)&T[d * 136 + o];
    }
}

// ---------------- fused kernel: gemm1 (blocks 0..375) + adjacency pack/echo (rest) ----------------
__global__ void __launch_bounds__(256) fused_pack_gemm1(
    const float* __restrict__ x, const float* __restrict__ W1,
    const int* __restrict__ adj, float* __restrict__ outf, long out_size)
{
    int bid = blockIdx.x;
    if (bid < G1_BLOCKS) {
        int h = bid / 47, ib = bid % 47;
        gemm_tf32_body<HID>(x, W1 + (size_t)h * F_IN * HID,
                            g_Wh + (size_t)h * N_NODES * HID,
                            g_WhT + (size_t)h * HID * JP,
                            ib * 128);
    } else {
        int gtid = (bid - G1_BLOCKS) * 256 + threadIdx.x;
        int warp = gtid >> 5, lane = gtid & 31;
        int row = warp / NW, wj = warp % NW;
        int j = wj * 32 + lane;
        int v = 0;
        if (j < N_NODES) {
            long idx = (long)row * N_NODES + j;
            v = adj[idx];
            long oi = (long)OUT_ADJ_OFF + idx;
            if (oi < out_size) outf[oi] = (float)v;
        }
        unsigned bits = __ballot_sync(0xFFFFFFFFu, v != 0);
        if (lane == 0) g_adjb[row * NW + wj] = bits;
    }
}

__global__ void __launch_bounds__(256) gemm2_kernel(const float* __restrict__ W2) {
    gemm_tf32_body<C_OUT>(g_h1, W2, g_Wh2, g_WhT2, blockIdx.x * 128);
}

// ---------------- kernel 3: per-node scores + packed {e,f} tables (layer 1) ----------------
__global__ void scores1_kernel(const float* __restrict__ a_src,
                               const float* __restrict__ a_tgt) {
    int gw = (blockIdx.x * blockDim.x + threadIdx.x) >> 5;
    int lane = threadIdx.x & 31;
    if (gw >= H1 * N_NODES) return;
    int h = gw / N_NODES, n = gw % N_NODES;
    const float* wh = &g_Wh[((size_t)h * N_NODES + n) * HID];
    float w1 = wh[lane], w2 = wh[lane + 32];
    float ss = w1 * a_src[h * HID + lane] + w2 * a_src[h * HID + lane + 32];
    float st = w1 * a_tgt[h * HID + lane] + w2 * a_tgt[h * HID + lane + 32];
    #pragma unroll
    for (int o = 16; o > 0; o >>= 1) {
        ss += __shfl_xor_sync(0xFFFFFFFFu, ss, o);
        st += __shfl_xor_sync(0xFFFFFFFFu, st, o);
    }
    if (lane == 0) {
        g_Ei[gw] = expf(ss); g_Fi[gw] = expf(ALPHA * ss);
        __half* pk = (__half*)&g_pk1[(size_t)h * (JP / 2) + (n >> 1)];
        int o = n & 1;
        pk[0 + o] = __float2half_rn(expf(st));
        pk[2 + o] = __float2half_rn(expf(ALPHA * st));
    }
}

// ---------------- fused masked-softmax AV on mma.sync ----------------
// 128 threads = 4 warps, 32 rows/warp (2 row-groups) -> 128 rows/block.
// w = mask * max(Ei*ej, Fi*fj). L1: j split 3-ways (balanced 2-blocks-per-slot waves).
template<int NG, int NGL, bool L2K>
__global__ void __launch_bounds__(128, 4) av_mma_kernel(float* __restrict__ dummy) {
    __shared__ __align__(16) __half Bbuf[3][64 * 72];
    __shared__ __align__(16) uint2  Pbuf[3][32];

    int tid = threadIdx.x;
    int lane = tid & 31, warp = tid >> 5;
    int i0 = blockIdx.x * 128;

    const float *Eiv, *Fiv;
    const uint2* pk;
    const __half* whT;
    int tbeg, NT, pidx, zcol;
    if (L2K) {
        Eiv = g_E2i; Fiv = g_F2i;
        pk = g_pk2; whT = g_WhT2;
        int y = blockIdx.y;
        tbeg = (y < 6) ? y * 12 : 72 + (y - 6) * 11;
        NT   = (y < 6) ? 12 : 11;
        pidx = y; zcol = 40;
    } else {
        int h = blockIdx.y;
        int hb = h * N_NODES;
        Eiv = g_Ei + hb; Fiv = g_Fi + hb;
        pk = g_pk1 + (size_t)h * (JP / 2);
        whT = g_WhT + (size_t)h * HID * JP;
        int z = blockIdx.z;                    // 3-way j split: 32,31,31
        tbeg = (z == 0) ? 0 : 32 + (z - 1) * 31;
        NT   = (z == 0) ? 32 : 31;
        pidx = h * 3 + z; zcol = 64;
    }

    // 4 row slots: r0 + {0,8,16,24}
    int r0 = i0 + warp * 32 + (lane >> 2);
    int rowc[4];
    __half2 E2[4], F2[4];
    #pragma unroll
    for (int s = 0; s < 4; s++) {
        rowc[s] = min(r0 + s * 8, N_NODES - 1);
        E2[s] = __half2half2(__float2half_rn(Eiv[rowc[s]]));
        F2[s] = __half2half2(__float2half_rn(Fiv[rowc[s]]));
    }
    int c4 = lane & 3, cb = c4 * 2;

    int nb = (lane & 7) | (((lane >> 4) & 1) << 3);
    int kb = ((lane >> 3) & 1) * 8;
    uint32_t bB[3] = { smem_u32(Bbuf[0]), smem_u32(Bbuf[1]), smem_u32(Bbuf[2]) };
    uint32_t lds_off = (uint32_t)(nb * 72 + kb) * 2;

    float acc[2][NG][4];
    float accz[2][4];
    #pragma unroll
    for (int g = 0; g < 2; g++) {
        #pragma unroll
        for (int n = 0; n < NG; n++)
            #pragma unroll
            for (int c = 0; c < 4; c++) acc[g][n][c] = 0.f;
        #pragma unroll
        for (int c = 0; c < 4; c++) accz[g][c] = 0.f;
    }

    const uint32_t ONES2 = 0x3C003C00u;
    const uint32_t bz[2] = { ONES2, ONES2 };

    auto stage = [&](int t, int b) {
        int j0 = (tbeg + t) * 64;
        #pragma unroll
        for (int i2 = 0; i2 < 4; i2++) {
            int c = tid + 128 * i2;
            int n = c >> 3, o = c & 7;
            CP_ASYNC16(bB[b] + (uint32_t)(n * 144 + o * 16),
                       whT + (size_t)n * JP + j0 + o * 8);
        }
        if (tid >= 96 && tid < 112) {
            int e = tid - 96;                  // 0..15, 2 uint2 entries each
            CP_ASYNC16(smem_u32(&Pbuf[b][e * 2]), pk + (j0 >> 1) + e * 2);
        }
    };

    stage(0, 0); CP_COMMIT();
    if (NT > 1) { stage(1, 1); CP_COMMIT(); }

    for (int t = 0; t < NT; t++) {
        int b = t % 3;
        if (t + 1 < NT) CP_WAIT1(); else CP_WAIT0();
        __syncthreads();
        if (t + 2 < NT) { stage(t + 2, (t + 2) % 3); CP_COMMIT(); }

        // adjacency words for this tile (L2-resident, latency covered by occupancy)
        uint2 aw[4];
        #pragma unroll
        for (int s = 0; s < 4; s++)
            aw[s] = *(const uint2*)&g_adjb[(size_t)rowc[s] * NW + 2 * (tbeg + t)];

        #pragma unroll
        for (int ks = 0; ks < 4; ks++) {
            uint2 p0 = Pbuf[b][ks * 8 + c4];
            uint2 p1 = Pbuf[b][ks * 8 + c4 + 4];
            __half2 eA = *(__half2*)&p0.x, fA = *(__half2*)&p0.y;
            __half2 eB = *(__half2*)&p1.x, fB = *(__half2*)&p1.y;

            int sh = ((ks & 1) << 4) + cb;
            // build A fragments for BOTH row groups first (8 regs)
            uint32_t a2[2][4];
            #pragma unroll
            for (int g = 0; g < 2; g++) {
                #pragma unroll
                for (int rr = 0; rr < 2; rr++) {
                    int s = g * 2 + rr;
                    unsigned word = (ks < 2) ? aw[s].x : aw[s].y;
                    unsigned ta = word >> sh;
                    unsigned tb2 = ta >> 8;
                    uint32_t ma = (ta  & 1u) * 0x3C00u + (ta  & 2u) * 0x1E000000u;
                    uint32_t mb = (tb2 & 1u) * 0x3C00u + (tb2 & 2u) * 0x1E000000u;

                    __half2 wa = __hmul2(
                        __hmax2(__hmul2(E2[s], eA), __hmul2(F2[s], fA)), *(__half2*)&ma);
                    __half2 wbv = __hmul2(
                        __hmax2(__hmul2(E2[s], eB), __hmul2(F2[s], fB)), *(__half2*)&mb);

                    a2[g][rr]     = *(uint32_t*)&wa;
                    a2[g][rr + 2] = *(uint32_t*)&wbv;
                }
            }
            // consume B fragments 4 regs at a time
            #pragma unroll
            for (int p = 0; p < NGL / 2; p++) {
                uint32_t bf0[2], bf1[2];
                ldsm_x4(bf0[0], bf0[1], bf1[0], bf1[1],
                        bB[b] + lds_off + (uint32_t)(p * 16 * 144 + ks * 32));
                int n0 = 2 * p, n1 = 2 * p + 1;
                if (n0 < NG) { mma_16816(acc[0][n0], a2[0], bf0); mma_16816(acc[1][n0], a2[1], bf0); }
                if (n1 < NG) { mma_16816(acc[0][n1], a2[0], bf1); mma_16816(acc[1][n1], a2[1], bf1); }
            }
            mma_16816(accz[0], a2[0], bz);
            mma_16816(accz[1], a2[1], bz);
        }
    }

    // ---- epilogue: partial store (D cols + Z) ----
    #pragma unroll
    for (int g = 0; g < 2; g++) {
        #pragma unroll
        for (int rr = 0; rr < 2; rr++) {
            int row = r0 + (g * 2 + rr) * 8;
            if (row >= N_NODES) continue;
            size_t base = ((size_t)pidx * 6016 + row) * 72;
            #pragma unroll
            for (int n = 0; n < NG; n++)
                *(float2*)&g_part[base + n * 8 + cb] =
                    make_float2(acc[g][n][rr * 2], acc[g][n][rr * 2 + 1]);
            if (cb == 0) g_part[base + zcol] = accz[g][rr * 2];
        }
    }
}

// ---------------- layer-1 combine (3 parts per head): normalize + ELU -> g_h1 ----------------
__global__ void combine1_kernel() {
    int idx = blockIdx.x * blockDim.x + threadIdx.x;   // over H1*N_NODES*32 float2 units
    if (idx >= H1 * N_NODES * 32) return;
    int c2 = idx & 31;
    int rest = idx >> 5;
    int row = rest % N_NODES;
    int h = rest / N_NODES;
    float na = 0.f, nb2 = 0.f, z = 0.f;
    #pragma unroll
    for (int k = 0; k < 3; k++) {
        size_t b = ((size_t)(h * 3 + k) * 6016 + row) * 72;
        float2 v = *(float2*)&g_part[b + c2 * 2];
        na += v.x; nb2 += v.y;
        z += g_part[b + 64];
    }
    float invZ = 1.0f / z;
    float a = na * invZ, b = nb2 * invZ;
    a = a > 0.f ? a : expm1f(a);
    b = b > 0.f ? b : expm1f(b);
    *(float2*)&g_h1[(size_t)row * (H1 * HID) + h * HID + c2 * 2] = make_float2(a, b);
}

// ---------------- layer-2 partial combine (8 parts) ----------------
__global__ void combine2_kernel(float* __restrict__ out) {
    int idx = blockIdx.x * blockDim.x + threadIdx.x;
    if (idx >= N_NODES * C_OUT) return;
    int row = idx / C_OUT, c = idx - row * C_OUT;
    float num = 0.f, z = 0.f;
    #pragma unroll
    for (int y = 0; y < 8; y++) {
        size_t b = ((size_t)y * 6016 + row) * 72;
        num += g_part[b + c];
        z   += g_part[b + 40];
    }
    out[idx] = num / z;
}

// ---------------- kernel 6: layer-2 scores (packed {e,f} table) ----------------
__global__ void scores2_kernel(const float* __restrict__ a_src2,
                               const float* __restrict__ a_tgt2) {
    int gw = (blockIdx.x * blockDim.x + threadIdx.x) >> 5;
    int lane = threadIdx.x & 31;
    if (gw >= N_NODES) return;
    float w1 = g_Wh2[(size_t)gw * C_OUT + lane];
    float as1 = a_src2[lane], at1 = a_tgt2[lane];
    float w2 = 0.f, as2 = 0.f, at2 = 0.f;
    if (lane + 32 < C_OUT) {
        w2 = g_Wh2[(size_t)gw * C_OUT + lane + 32];
        as2 = a_src2[lane + 32]; at2 = a_tgt2[lane + 32];
    }
    float ss = w1 * as1 + w2 * as2;
    float st = w1 * at1 + w2 * at2;
    #pragma unroll
    for (int o = 16; o > 0; o >>= 1) {
        ss += __shfl_xor_sync(0xFFFFFFFFu, ss, o);
        st += __shfl_xor_sync(0xFFFFFFFFu, st, o);
    }
    if (lane == 0) {
        g_E2i[gw] = expf(ss); g_F2i[gw] = expf(ALPHA * ss);
        __half* pkw = (__half*)&g_pk2[gw >> 1];
        int o = gw & 1;
        pkw[0 + o] = __float2half_rn(expf(st));
        pkw[2 + o] = __float2half_rn(expf(ALPHA * st));
    }
}

// ---------------- launch ----------------
extern "C" void kernel_launch(void* const* d_in, const int* in_sizes, int n_in,
                              void* d_out, int out_size) {
    const float* x      = (const float*)d_in[0];
    const int*   adj    = (const int*)  d_in[1];
    const float* W1     = (const float*)d_in[2];
    const float* a_src1 = (const float*)d_in[3];
    const float* a_tgt1 = (const float*)d_in[4];
    const float* W2     = (const float*)d_in[5];
    const float* a_src2 = (const float*)d_in[6];
    const float* a_tgt2 = (const float*)d_in[7];
    float* out = (float*)d_out;

    // fused: gemm1 (compute-bound) + adjacency pack/echo (HBM-bound) overlap
    fused_pack_gemm1<<<G1_BLOCKS + PACK_BLOCKS, 256>>>(x, W1, adj, out, (long)out_size);

    scores1_kernel<<<(H1 * N_NODES * 32 + 255) / 256, 256>>>(a_src1, a_tgt1);
    av_mma_kernel<8, 8, false><<<dim3(JP / 128, H1, 3), 128>>>(nullptr);
    combine1_kernel<<<(H1 * N_NODES * 32 + 255) / 256, 256>>>();

    gemm2_kernel<<<(N_NODES + 127) / 128, 256>>>(W2);
    scores2_kernel<<<(N_NODES * 32 + 255) / 256, 256>>>(a_src2, a_tgt2);
    av_mma_kernel<5, 6, true><<<dim3(JP / 128, 8), 128>>>(nullptr);
    combine2_kernel<<<(N_NODES * C_OUT + 255) / 256, 256>>>(out);
}

// round 14
// speedup vs baseline: 1.1938x; 1.1938x over previous
#include <cuda_runtime.h>
#include <cuda_fp16.h>
#include <math.h>
#include <stdint.h>

// ---------------- problem constants ----------------
#define N_NODES 6000
#define JP      6016           // N padded to multiple of 64
#define F_IN    512
#define HID     64
#define H1      8
#define C_OUT   40
#define NW      188
#define ALPHA   0.2f
#define OUT_ADJ_OFF (N_NODES * C_OUT)
#define NT_FULL 94             // JP/64

// ---------------- device scratch ----------------
__device__ float    g_Wh  [H1 * N_NODES * HID];
__device__ __half   g_WhT [H1 * HID * (size_t)JP];
__device__ unsigned g_adjb[N_NODES * NW];
__device__ float    g_h1  [N_NODES * (H1 * HID)];
__device__ float    g_Wh2 [N_NODES * C_OUT];
__device__ __half   g_WhT2[HID * (size_t)JP];
__device__ float    g_part[24 * 6016 * 72];      // partials: stride 72; L1 Z@64, L2 Z@40

__device__ float  g_Ei[H1 * N_NODES], g_Fi[H1 * N_NODES];
__device__ float  g_E2i[N_NODES], g_F2i[N_NODES];
// packed per-j tables: entry (j/2) = { e2, f2 } halves; zero in pad region
__device__ uint2  g_pk1[H1 * (JP / 2)];
__device__ uint2  g_pk2[JP / 2];

// ---------------- helpers ----------------
__device__ __forceinline__ uint32_t smem_u32(const void* p) {
    uint32_t a;
    asm("{ .reg .u64 t; cvta.to.shared.u64 t, %1; cvt.u32.u64 %0, t; }" : "=r"(a) : "l"(p));
    return a;
}
__device__ __forceinline__ void mma_16816(float c[4], const uint32_t a[4], const uint32_t b[2]) {
    asm volatile(
        "mma.sync.aligned.m16n8k16.row.col.f32.f16.f16.f32 "
        "{%0,%1,%2,%3}, {%4,%5,%6,%7}, {%8,%9}, {%0,%1,%2,%3};"
        : "+f"(c[0]), "+f"(c[1]), "+f"(c[2]), "+f"(c[3])
        : "r"(a[0]), "r"(a[1]), "r"(a[2]), "r"(a[3]), "r"(b[0]), "r"(b[1]));
}
__device__ __forceinline__ void mma_tf32(float c[4], const uint32_t a[4], const uint32_t b[2]) {
    asm volatile(
        "mma.sync.aligned.m16n8k8.row.col.f32.tf32.tf32.f32 "
        "{%0,%1,%2,%3}, {%4,%5,%6,%7}, {%8,%9}, {%0,%1,%2,%3};"
        : "+f"(c[0]), "+f"(c[1]), "+f"(c[2]), "+f"(c[3])
        : "r"(a[0]), "r"(a[1]), "r"(a[2]), "r"(a[3]), "r"(b[0]), "r"(b[1]));
}
__device__ __forceinline__ void ldsm_x4(uint32_t& r0, uint32_t& r1, uint32_t& r2, uint32_t& r3,
                                        uint32_t addr) {
    asm volatile("ldmatrix.sync.aligned.m8n8.x4.shared.b16 {%0,%1,%2,%3}, [%4];"
                 : "=r"(r0), "=r"(r1), "=r"(r2), "=r"(r3) : "r"(addr));
}
__device__ __forceinline__ uint32_t tf32_of(float x) {
    uint32_t r;
    asm("cvt.rna.tf32.f32 %0, %1;" : "=r"(r) : "f"(x));
    return r;
}
#define CP_ASYNC16(dst, src) \
    asm volatile("cp.async.cg.shared.global [%0], [%1], 16;" :: "r"(dst), "l"(src))
#define CP_COMMIT() asm volatile("cp.async.commit_group;" ::: "memory")
#define CP_WAIT1()  asm volatile("cp.async.wait_group 1;" ::: "memory")
#define CP_WAIT0()  asm volatile("cp.async.wait_group 0;" ::: "memory")

// ---------------- kernel 1: pack adjacency + echo adj to output (standalone, lean) ----------------
__global__ void pack_adj_kernel(const int* __restrict__ adj,
                                float* __restrict__ outf, long out_size) {
    int gtid = blockIdx.x * blockDim.x + threadIdx.x;
    int warp = gtid >> 5, lane = gtid & 31;
    int row = warp / NW, wj = warp % NW;
    int j = wj * 32 + lane;
    int v = 0;
    if (j < N_NODES) {
        long idx = (long)row * N_NODES + j;
        v = adj[idx];
        long oi = (long)OUT_ADJ_OFF + idx;
        if (oi < out_size) outf[oi] = (float)v;
    }
    unsigned bits = __ballot_sync(0xFFFFFFFFu, v != 0);
    if (lane == 0) g_adjb[row * NW + wj] = bits;
}

// ---------------- tf32 GEMM template body (256 threads) ----------------
template<int NB>
__device__ __forceinline__ void gemm_tf32_body(
    const float* __restrict__ Asrc,
    const float* __restrict__ Bsrc,
    float* __restrict__ Cout,
    __half* __restrict__ CtT,
    int i0)
{
    __shared__ __align__(16) char sbuf[17408];
    float* As = (float*)sbuf;                 // [128][20]
    float* Bs = (float*)(sbuf + 10240);       // [16][72]
    __half* T = (__half*)sbuf;                // [64][136] reused after mainloop

    int tid = threadIdx.x;
    int lane = tid & 31, warp = tid >> 5;
    int wr = warp >> 1, wc = warp & 1;

    float acc[2][4][4];
    #pragma unroll
    for (int m = 0; m < 2; m++)
        #pragma unroll
        for (int n = 0; n < 4; n++)
            #pragma unroll
            for (int c = 0; c < 4; c++) acc[m][n][c] = 0.f;

    int sr = tid >> 1, skk = (tid & 1) * 8;
    int bkk = tid >> 4, bn0 = (tid & 15) * 4;

    for (int k0 = 0; k0 < F_IN; k0 += 16) {
        {
            float4 v0 = make_float4(0.f, 0.f, 0.f, 0.f), v1 = v0;
            if (i0 + sr < N_NODES) {
                const float* src = &Asrc[(size_t)(i0 + sr) * F_IN + k0 + skk];
                v0 = *(const float4*)src;
                v1 = *(const float4*)(src + 4);
            }
            uint32_t* d = (uint32_t*)&As[sr * 20 + skk];
            d[0] = tf32_of(v0.x); d[1] = tf32_of(v0.y); d[2] = tf32_of(v0.z); d[3] = tf32_of(v0.w);
            d[4] = tf32_of(v1.x); d[5] = tf32_of(v1.y); d[6] = tf32_of(v1.z); d[7] = tf32_of(v1.w);
        }
        {
            float4 b = make_float4(0.f, 0.f, 0.f, 0.f);
            if (bn0 < NB)
                b = *(const float4*)&Bsrc[(size_t)(k0 + bkk) * NB + bn0];
            uint32_t* d = (uint32_t*)&Bs[bkk * 72 + bn0];
            d[0] = tf32_of(b.x); d[1] = tf32_of(b.y); d[2] = tf32_of(b.z); d[3] = tf32_of(b.w);
        }
        __syncthreads();

        #pragma unroll
        for (int s = 0; s < 2; s++) {
            int arow = wr * 32 + (lane >> 2);
            int akol = s * 8 + (lane & 3);
            uint32_t af[2][4];
            #pragma unroll
            for (int m = 0; m < 2; m++) {
                int base = (arow + m * 16) * 20 + akol;
                af[m][0] = __float_as_uint(As[base]);
                af[m][1] = __float_as_uint(As[base + 8 * 20]);
                af[m][2] = __float_as_uint(As[base + 4]);
                af[m][3] = __float_as_uint(As[base + 8 * 20 + 4]);
            }
            int bb = (s * 8 + (lane & 3)) * 72 + wc * 32 + (lane >> 2);
            uint32_t bf[4][2];
            #pragma unroll
            for (int n = 0; n < 4; n++) {
                bf[n][0] = __float_as_uint(Bs[bb + n * 8]);
                bf[n][1] = __float_as_uint(Bs[bb + n * 8 + 4 * 72]);
            }
            #pragma unroll
            for (int m = 0; m < 2; m++)
                #pragma unroll
                for (int n = 0; n < 4; n++)
                    mma_tf32(acc[m][n], af[m], bf[n]);
        }
        __syncthreads();
    }

    int rl = wr * 32 + (lane >> 2);
    int cbx = wc * 32 + (lane & 3) * 2;
    #pragma unroll
    for (int m = 0; m < 2; m++) {
        int r0 = rl + m * 16, r1 = r0 + 8;
        #pragma unroll
        for (int n = 0; n < 4; n++) {
            int c = cbx + n * 8;
            if (c < NB) {
                if (i0 + r0 < N_NODES)
                    *(float2*)&Cout[(size_t)(i0 + r0) * NB + c] =
                        make_float2(acc[m][n][0], acc[m][n][1]);
                if (i0 + r1 < N_NODES)
                    *(float2*)&Cout[(size_t)(i0 + r1) * NB + c] =
                        make_float2(acc[m][n][2], acc[m][n][3]);
            }
            T[(c + 0) * 136 + r0] = __float2half_rn(acc[m][n][0]);
            T[(c + 1) * 136 + r0] = __float2half_rn(acc[m][n][1]);
            T[(c + 0) * 136 + r1] = __float2half_rn(acc[m][n][2]);
            T[(c + 1) * 136 + r1] = __float2half_rn(acc[m][n][3]);
        }
    }
    __syncthreads();
    #pragma unroll
    for (int q = 0; q < 4; q++) {
        int l = tid + 256 * q;               // 0..1023
        int d = l >> 4, o = (l & 15) * 8;
        *(uint4*)&CtT[(size_t)d * JP + i0 + o] = *(uint4*)&T[d * 136 + o];
    }
}

__global__ void __launch_bounds__(256) gemm1_kernel(const float* __restrict__ x,
                                                    const float* __restrict__ W1) {
    int h = blockIdx.y;
    gemm_tf32_body<HID>(x, W1 + (size_t)h * F_IN * HID,
                        g_Wh + (size_t)h * N_NODES * HID,
                        g_WhT + (size_t)h * HID * JP,
                        blockIdx.x * 128);
}

__global__ void __launch_bounds__(256) gemm2_kernel(const float* __restrict__ W2) {
    gemm_tf32_body<C_OUT>(g_h1, W2, g_Wh2, g_WhT2, blockIdx.x * 128);
}

// ---------------- kernel 3: per-node scores + packed {e,f} tables (layer 1) ----------------
__global__ void scores1_kernel(const float* __restrict__ a_src,
                               const float* __restrict__ a_tgt) {
    int gw = (blockIdx.x * blockDim.x + threadIdx.x) >> 5;
    int lane = threadIdx.x & 31;
    if (gw >= H1 * N_NODES) return;
    int h = gw / N_NODES, n = gw % N_NODES;
    const float* wh = &g_Wh[((size_t)h * N_NODES + n) * HID];
    float w1 = wh[lane], w2 = wh[lane + 32];
    float ss = w1 * a_src[h * HID + lane] + w2 * a_src[h * HID + lane + 32];
    float st = w1 * a_tgt[h * HID + lane] + w2 * a_tgt[h * HID + lane + 32];
    #pragma unroll
    for (int o = 16; o > 0; o >>= 1) {
        ss += __shfl_xor_sync(0xFFFFFFFFu, ss, o);
        st += __shfl_xor_sync(0xFFFFFFFFu, st, o);
    }
    if (lane == 0) {
        g_Ei[gw] = expf(ss); g_Fi[gw] = expf(ALPHA * ss);
        __half* pk = (__half*)&g_pk1[(size_t)h * (JP / 2) + (n >> 1)];
        int o = n & 1;
        pk[0 + o] = __float2half_rn(expf(st));
        pk[2 + o] = __float2half_rn(expf(ALPHA * st));
    }
}

// ---------------- fused masked-softmax AV on mma.sync ----------------
// 128 threads = 4 warps, 32 rows/warp (2 row-groups) -> 128 rows/block.
// w = mask * max(Ei*ej, Fi*fj). L1: j split 3-ways (balanced 2-blocks-per-slot waves).
template<int NG, int NGL, bool L2K>
__global__ void __launch_bounds__(128, 4) av_mma_kernel(float* __restrict__ dummy) {
    __shared__ __align__(16) __half Bbuf[3][64 * 72];
    __shared__ __align__(16) uint2  Pbuf[3][32];

    int tid = threadIdx.x;
    int lane = tid & 31, warp = tid >> 5;
    int i0 = blockIdx.x * 128;

    const float *Eiv, *Fiv;
    const uint2* pk;
    const __half* whT;
    int tbeg, NT, pidx, zcol;
    if (L2K) {
        Eiv = g_E2i; Fiv = g_F2i;
        pk = g_pk2; whT = g_WhT2;
        int y = blockIdx.y;
        tbeg = (y < 6) ? y * 12 : 72 + (y - 6) * 11;
        NT   = (y < 6) ? 12 : 11;
        pidx = y; zcol = 40;
    } else {
        int h = blockIdx.y;
        int hb = h * N_NODES;
        Eiv = g_Ei + hb; Fiv = g_Fi + hb;
        pk = g_pk1 + (size_t)h * (JP / 2);
        whT = g_WhT + (size_t)h * HID * JP;
        int z = blockIdx.z;                    // 3-way j split: 32,31,31
        tbeg = (z == 0) ? 0 : 32 + (z - 1) * 31;
        NT   = (z == 0) ? 32 : 31;
        pidx = h * 3 + z; zcol = 64;
    }

    // 4 row slots: r0 + {0,8,16,24}
    int r0 = i0 + warp * 32 + (lane >> 2);
    int rowc[4];
    __half2 E2[4], F2[4];
    #pragma unroll
    for (int s = 0; s < 4; s++) {
        rowc[s] = min(r0 + s * 8, N_NODES - 1);
        E2[s] = __half2half2(__float2half_rn(Eiv[rowc[s]]));
        F2[s] = __half2half2(__float2half_rn(Fiv[rowc[s]]));
    }
    int c4 = lane & 3, cb = c4 * 2;

    int nb = (lane & 7) | (((lane >> 4) & 1) << 3);
    int kb = ((lane >> 3) & 1) * 8;
    uint32_t bB[3] = { smem_u32(Bbuf[0]), smem_u32(Bbuf[1]), smem_u32(Bbuf[2]) };
    uint32_t lds_off = (uint32_t)(nb * 72 + kb) * 2;

    float acc[2][NG][4];
    float accz[2][4];
    #pragma unroll
    for (int g = 0; g < 2; g++) {
        #pragma unroll
        for (int n = 0; n < NG; n++)
            #pragma unroll
            for (int c = 0; c < 4; c++) acc[g][n][c] = 0.f;
        #pragma unroll
        for (int c = 0; c < 4; c++) accz[g][c] = 0.f;
    }

    const uint32_t ONES2 = 0x3C003C00u;
    const uint32_t bz[2] = { ONES2, ONES2 };

    auto stage = [&](int t, int b) {
        int j0 = (tbeg + t) * 64;
        #pragma unroll
        for (int i2 = 0; i2 < 4; i2++) {
            int c = tid + 128 * i2;
            int n = c >> 3, o = c & 7;
            CP_ASYNC16(bB[b] + (uint32_t)(n * 144 + o * 16),
                       whT + (size_t)n * JP + j0 + o * 8);
        }
        if (tid >= 96 && tid < 112) {
            int e = tid - 96;                  // 0..15, 2 uint2 entries each
            CP_ASYNC16(smem_u32(&Pbuf[b][e * 2]), pk + (j0 >> 1) + e * 2);
        }
    };

    stage(0, 0); CP_COMMIT();
    if (NT > 1) { stage(1, 1); CP_COMMIT(); }

    for (int t = 0; t < NT; t++) {
        int b = t % 3;
        if (t + 1 < NT) CP_WAIT1(); else CP_WAIT0();
        __syncthreads();
        if (t + 2 < NT) { stage(t + 2, (t + 2) % 3); CP_COMMIT(); }

        // adjacency words for this tile (L2-resident, latency covered by occupancy)
        uint2 aw[4];
        #pragma unroll
        for (int s = 0; s < 4; s++)
            aw[s] = *(const uint2*)&g_adjb[(size_t)rowc[s] * NW + 2 * (tbeg + t)];

        #pragma unroll
        for (int ks = 0; ks < 4; ks++) {
            uint2 p0 = Pbuf[b][ks * 8 + c4];
            uint2 p1 = Pbuf[b][ks * 8 + c4 + 4];
            __half2 eA = *(__half2*)&p0.x, fA = *(__half2*)&p0.y;
            __half2 eB = *(__half2*)&p1.x, fB = *(__half2*)&p1.y;

            int sh = ((ks & 1) << 4) + cb;
            // build A fragments for BOTH row groups first (8 regs)
            uint32_t a2[2][4];
            #pragma unroll
            for (int g = 0; g < 2; g++) {
                #pragma unroll
                for (int rr = 0; rr < 2; rr++) {
                    int s = g * 2 + rr;
                    unsigned word = (ks < 2) ? aw[s].x : aw[s].y;
                    unsigned ta = word >> sh;
                    unsigned tb2 = ta >> 8;
                    uint32_t ma = (ta  & 1u) * 0x3C00u + (ta  & 2u) * 0x1E000000u;
                    uint32_t mb = (tb2 & 1u) * 0x3C00u + (tb2 & 2u) * 0x1E000000u;

                    __half2 wa = __hmul2(
                        __hmax2(__hmul2(E2[s], eA), __hmul2(F2[s], fA)), *(__half2*)&ma);
                    __half2 wbv = __hmul2(
                        __hmax2(__hmul2(E2[s], eB), __hmul2(F2[s], fB)), *(__half2*)&mb);

                    a2[g][rr]     = *(uint32_t*)&wa;
                    a2[g][rr + 2] = *(uint32_t*)&wbv;
                }
            }
            // consume B fragments 4 regs at a time
            #pragma unroll
            for (int p = 0; p < NGL / 2; p++) {
                uint32_t bf0[2], bf1[2];
                ldsm_x4(bf0[0], bf0[1], bf1[0], bf1[1],
                        bB[b] + lds_off + (uint32_t)(p * 16 * 144 + ks * 32));
                int n0 = 2 * p, n1 = 2 * p + 1;
                if (n0 < NG) { mma_16816(acc[0][n0], a2[0], bf0); mma_16816(acc[1][n0], a2[1], bf0); }
                if (n1 < NG) { mma_16816(acc[0][n1], a2[0], bf1); mma_16816(acc[1][n1], a2[1], bf1); }
            }
            mma_16816(accz[0], a2[0], bz);
            mma_16816(accz[1], a2[1], bz);
        }
    }

    // ---- epilogue: partial store (D cols + Z) ----
    #pragma unroll
    for (int g = 0; g < 2; g++) {
        #pragma unroll
        for (int rr = 0; rr < 2; rr++) {
            int row = r0 + (g * 2 + rr) * 8;
            if (row >= N_NODES) continue;
            size_t base = ((size_t)pidx * 6016 + row) * 72;
            #pragma unroll
            for (int n = 0; n < NG; n++)
                *(float2*)&g_part[base + n * 8 + cb] =
                    make_float2(acc[g][n][rr * 2], acc[g][n][rr * 2 + 1]);
            if (cb == 0) g_part[base + zcol] = accz[g][rr * 2];
        }
    }
}

// ---------------- layer-1 combine (3 parts per head): normalize + ELU -> g_h1 ----------------
__global__ void combine1_kernel() {
    int idx = blockIdx.x * blockDim.x + threadIdx.x;   // over H1*N_NODES*32 float2 units
    if (idx >= H1 * N_NODES * 32) return;
    int c2 = idx & 31;
    int rest = idx >> 5;
    int row = rest % N_NODES;
    int h = rest / N_NODES;
    float na = 0.f, nb2 = 0.f, z = 0.f;
    #pragma unroll
    for (int k = 0; k < 3; k++) {
        size_t b = ((size_t)(h * 3 + k) * 6016 + row) * 72;
        float2 v = *(float2*)&g_part[b + c2 * 2];
        na += v.x; nb2 += v.y;
        z += g_part[b + 64];
    }
    float invZ = 1.0f / z;
    float a = na * invZ, b = nb2 * invZ;
    a = a > 0.f ? a : expm1f(a);
    b = b > 0.f ? b : expm1f(b);
    *(float2*)&g_h1[(size_t)row * (H1 * HID) + h * HID + c2 * 2] = make_float2(a, b);
}

// ---------------- layer-2 partial combine (8 parts) ----------------
__global__ void combine2_kernel(float* __restrict__ out) {
    int idx = blockIdx.x * blockDim.x + threadIdx.x;
    if (idx >= N_NODES * C_OUT) return;
    int row = idx / C_OUT, c = idx - row * C_OUT;
    float num = 0.f, z = 0.f;
    #pragma unroll
    for (int y = 0; y < 8; y++) {
        size_t b = ((size_t)y * 6016 + row) * 72;
        num += g_part[b + c];
        z   += g_part[b + 40];
    }
    out[idx] = num / z;
}

// ---------------- kernel 6: layer-2 scores (packed {e,f} table) ----------------
__global__ void scores2_kernel(const float* __restrict__ a_src2,
                               const float* __restrict__ a_tgt2) {
    int gw = (blockIdx.x * blockDim.x + threadIdx.x) >> 5;
    int lane = threadIdx.x & 31;
    if (gw >= N_NODES) return;
    float w1 = g_Wh2[(size_t)gw * C_OUT + lane];
    float as1 = a_src2[lane], at1 = a_tgt2[lane];
    float w2 = 0.f, as2 = 0.f, at2 = 0.f;
    if (lane + 32 < C_OUT) {
        w2 = g_Wh2[(size_t)gw * C_OUT + lane + 32];
        as2 = a_src2[lane + 32]; at2 = a_tgt2[lane + 32];
    }
    float ss = w1 * as1 + w2 * as2;
    float st = w1 * at1 + w2 * at2;
    #pragma unroll
    for (int o = 16; o > 0; o >>= 1) {
        ss += __shfl_xor_sync(0xFFFFFFFFu, ss, o);
        st += __shfl_xor_sync(0xFFFFFFFFu, st, o);
    }
    if (lane == 0) {
        g_E2i[gw] = expf(ss); g_F2i[gw] = expf(ALPHA * ss);
        __half* pkw = (__half*)&g_pk2[gw >> 1];
        int o = gw & 1;
        pkw[0 + o] = __float2half_rn(expf(st));
        pkw[2 + o] = __float2half_rn(expf(ALPHA * st));
    }
}

// ---------------- launch ----------------
extern "C" void kernel_launch(void* const* d_in, const int* in_sizes, int n_in,
                              void* d_out, int out_size) {
    const float* x      = (const float*)d_in[0];
    const int*   adj    = (const int*)  d_in[1];
    const float* W1     = (const float*)d_in[2];
    const float* a_src1 = (const float*)d_in[3];
    const float* a_tgt1 = (const float*)d_in[4];
    const float* W2     = (const float*)d_in[5];
    const float* a_src2 = (const float*)d_in[6];
    const float* a_tgt2 = (const float*)d_in[7];
    float* out = (float*)d_out;

    pack_adj_kernel<<<(N_NODES * NW * 32) / 256, 256>>>(adj, out, (long)out_size);

    gemm1_kernel<<<dim3((N_NODES + 127) / 128, H1), 256>>>(x, W1);
    scores1_kernel<<<(H1 * N_NODES * 32 + 255) / 256, 256>>>(a_src1, a_tgt1);
    av_mma_kernel<8, 8, false><<<dim3(JP / 128, H1, 3), 128>>>(nullptr);
    combine1_kernel<<<(H1 * N_NODES * 32 + 255) / 256, 256>>>();

    gemm2_kernel<<<(N_NODES + 127) / 128, 256>>>(W2);
    scores2_kernel<<<(N_NODES * 32 + 255) / 256, 256>>>(a_src2, a_tgt2);
    av_mma_kernel<5, 6, true><<<dim3(JP / 128, 8), 128>>>(nullptr);
    combine2_kernel<<<(N_NODES * C_OUT + 255) / 256, 256>>>(out);
}

// round 15
// speedup vs baseline: 1.2062x; 1.0104x over previous
#include <cuda_runtime.h>
#include <cuda_fp16.h>
#include <math.h>
#include <stdint.h>

// ---------------- problem constants ----------------
#define N_NODES 6000
#define JP      6016           // N padded to multiple of 64
#define F_IN    512
#define HID     64
#define H1      8
#define C_OUT   40
#define NW      188
#define ALPHA   0.2f
#define OUT_ADJ_OFF (N_NODES * C_OUT)
#define NT_FULL 94             // JP/64

// ---------------- device scratch ----------------
__device__ float    g_Wh  [H1 * N_NODES * HID];
__device__ __half   g_WhT [H1 * HID * (size_t)JP];
__device__ unsigned g_adjb[N_NODES * NW];
__device__ float    g_h1  [N_NODES * (H1 * HID)];
__device__ float    g_Wh2 [N_NODES * C_OUT];
__device__ __half   g_WhT2[HID * (size_t)JP];
__device__ float    g_part[24 * 6016 * 72];      // partials: stride 72; L1 Z@64, L2 Z@40

__device__ float  g_Ei[H1 * N_NODES], g_Fi[H1 * N_NODES];
__device__ float  g_E2i[N_NODES], g_F2i[N_NODES];
// packed per-j tables: entry (j/2) = { e2, f2 } halves; zero in pad region
__device__ uint2  g_pk1[H1 * (JP / 2)];
__device__ uint2  g_pk2[JP / 2];

// ---------------- helpers ----------------
__device__ __forceinline__ uint32_t smem_u32(const void* p) {
    uint32_t a;
    asm("{ .reg .u64 t; cvta.to.shared.u64 t, %1; cvt.u32.u64 %0, t; }" : "=r"(a) : "l"(p));
    return a;
}
__device__ __forceinline__ void mma_16816(float c[4], const uint32_t a[4], const uint32_t b[2]) {
    asm volatile(
        "mma.sync.aligned.m16n8k16.row.col.f32.f16.f16.f32 "
        "{%0,%1,%2,%3}, {%4,%5,%6,%7}, {%8,%9}, {%0,%1,%2,%3};"
        : "+f"(c[0]), "+f"(c[1]), "+f"(c[2]), "+f"(c[3])
        : "r"(a[0]), "r"(a[1]), "r"(a[2]), "r"(a[3]), "r"(b[0]), "r"(b[1]));
}
__device__ __forceinline__ void mma_tf32(float c[4], const uint32_t a[4], const uint32_t b[2]) {
    asm volatile(
        "mma.sync.aligned.m16n8k8.row.col.f32.tf32.tf32.f32 "
        "{%0,%1,%2,%3}, {%4,%5,%6,%7}, {%8,%9}, {%0,%1,%2,%3};"
        : "+f"(c[0]), "+f"(c[1]), "+f"(c[2]), "+f"(c[3])
        : "r"(a[0]), "r"(a[1]), "r"(a[2]), "r"(a[3]), "r"(b[0]), "r"(b[1]));
}
__device__ __forceinline__ void ldsm_x4(uint32_t& r0, uint32_t& r1, uint32_t& r2, uint32_t& r3,
                                        uint32_t addr) {
    asm volatile("ldmatrix.sync.aligned.m8n8.x4.shared.b16 {%0,%1,%2,%3}, [%4];"
                 : "=r"(r0), "=r"(r1), "=r"(r2), "=r"(r3) : "r"(addr));
}
__device__ __forceinline__ uint32_t tf32_of(float x) {
    uint32_t r;
    asm("cvt.rna.tf32.f32 %0, %1;" : "=r"(r) : "f"(x));
    return r;
}
#define CP_ASYNC16(dst, src) \
    asm volatile("cp.async.cg.shared.global [%0], [%1], 16;" :: "r"(dst), "l"(src))
#define CP_ASYNC8(dst, src) \
    asm volatile("cp.async.ca.shared.global [%0], [%1], 8;" :: "r"(dst), "l"(src))
#define CP_COMMIT() asm volatile("cp.async.commit_group;" ::: "memory")
#define CP_WAIT1()  asm volatile("cp.async.wait_group 1;" ::: "memory")
#define CP_WAIT0()  asm volatile("cp.async.wait_group 0;" ::: "memory")

// ---------------- kernel 1: pack adjacency + echo adj to output ----------------
__global__ void pack_adj_kernel(const int* __restrict__ adj,
                                float* __restrict__ outf, long out_size) {
    int gtid = blockIdx.x * blockDim.x + threadIdx.x;
    int warp = gtid >> 5, lane = gtid & 31;
    int row = warp / NW, wj = warp % NW;
    int j = wj * 32 + lane;
    int v = 0;
    if (j < N_NODES) {
        long idx = (long)row * N_NODES + j;
        v = adj[idx];
        long oi = (long)OUT_ADJ_OFF + idx;
        if (oi < out_size) outf[oi] = (float)v;
    }
    unsigned bits = __ballot_sync(0xFFFFFFFFu, v != 0);
    if (lane == 0) g_adjb[row * NW + wj] = bits;
}

// ---------------- tf32 GEMM template body (256 threads) ----------------
template<int NB>
__device__ __forceinline__ void gemm_tf32_body(
    const float* __restrict__ Asrc,
    const float* __restrict__ Bsrc,
    float* __restrict__ Cout,
    __half* __restrict__ CtT,
    int i0)
{
    __shared__ __align__(16) char sbuf[17408];
    float* As = (float*)sbuf;                 // [128][20]
    float* Bs = (float*)(sbuf + 10240);       // [16][72]
    __half* T = (__half*)sbuf;                // [64][136] reused after mainloop

    int tid = threadIdx.x;
    int lane = tid & 31, warp = tid >> 5;
    int wr = warp >> 1, wc = warp & 1;

    float acc[2][4][4];
    #pragma unroll
    for (int m = 0; m < 2; m++)
        #pragma unroll
        for (int n = 0; n < 4; n++)
            #pragma unroll
            for (int c = 0; c < 4; c++) acc[m][n][c] = 0.f;

    int sr = tid >> 1, skk = (tid & 1) * 8;
    int bkk = tid >> 4, bn0 = (tid & 15) * 4;

    for (int k0 = 0; k0 < F_IN; k0 += 16) {
        {
            float4 v0 = make_float4(0.f, 0.f, 0.f, 0.f), v1 = v0;
            if (i0 + sr < N_NODES) {
                const float* src = &Asrc[(size_t)(i0 + sr) * F_IN + k0 + skk];
                v0 = *(const float4*)src;
                v1 = *(const float4*)(src + 4);
            }
            uint32_t* d = (uint32_t*)&As[sr * 20 + skk];
            d[0] = tf32_of(v0.x); d[1] = tf32_of(v0.y); d[2] = tf32_of(v0.z); d[3] = tf32_of(v0.w);
            d[4] = tf32_of(v1.x); d[5] = tf32_of(v1.y); d[6] = tf32_of(v1.z); d[7] = tf32_of(v1.w);
        }
        {
            float4 b = make_float4(0.f, 0.f, 0.f, 0.f);
            if (bn0 < NB)
                b = *(const float4*)&Bsrc[(size_t)(k0 + bkk) * NB + bn0];
            uint32_t* d = (uint32_t*)&Bs[bkk * 72 + bn0];
            d[0] = tf32_of(b.x); d[1] = tf32_of(b.y); d[2] = tf32_of(b.z); d[3] = tf32_of(b.w);
        }
        __syncthreads();

        #pragma unroll
        for (int s = 0; s < 2; s++) {
            int arow = wr * 32 + (lane >> 2);
            int akol = s * 8 + (lane & 3);
            uint32_t af[2][4];
            #pragma unroll
            for (int m = 0; m < 2; m++) {
                int base = (arow + m * 16) * 20 + akol;
                af[m][0] = __float_as_uint(As[base]);
                af[m][1] = __float_as_uint(As[base + 8 * 20]);
                af[m][2] = __float_as_uint(As[base + 4]);
                af[m][3] = __float_as_uint(As[base + 8 * 20 + 4]);
            }
            int bb = (s * 8 + (lane & 3)) * 72 + wc * 32 + (lane >> 2);
            uint32_t bf[4][2];
            #pragma unroll
            for (int n = 0; n < 4; n++) {
                bf[n][0] = __float_as_uint(Bs[bb + n * 8]);
                bf[n][1] = __float_as_uint(Bs[bb + n * 8 + 4 * 72]);
            }
            #pragma unroll
            for (int m = 0; m < 2; m++)
                #pragma unroll
                for (int n = 0; n < 4; n++)
                    mma_tf32(acc[m][n], af[m], bf[n]);
        }
        __syncthreads();
    }

    int rl = wr * 32 + (lane >> 2);
    int cbx = wc * 32 + (lane & 3) * 2;
    #pragma unroll
    for (int m = 0; m < 2; m++) {
        int r0 = rl + m * 16, r1 = r0 + 8;
        #pragma unroll
        for (int n = 0; n < 4; n++) {
            int c = cbx + n * 8;
            if (c < NB) {
                if (i0 + r0 < N_NODES)
                    *(float2*)&Cout[(size_t)(i0 + r0) * NB + c] =
                        make_float2(acc[m][n][0], acc[m][n][1]);
                if (i0 + r1 < N_NODES)
                    *(float2*)&Cout[(size_t)(i0 + r1) * NB + c] =
                        make_float2(acc[m][n][2], acc[m][n][3]);
            }
            T[(c + 0) * 136 + r0] = __float2half_rn(acc[m][n][0]);
            T[(c + 1) * 136 + r0] = __float2half_rn(acc[m][n][1]);
            T[(c + 0) * 136 + r1] = __float2half_rn(acc[m][n][2]);
            T[(c + 1) * 136 + r1] = __float2half_rn(acc[m][n][3]);
        }
    }
    __syncthreads();
    #pragma unroll
    for (int q = 0; q < 4; q++) {
        int l = tid + 256 * q;               // 0..1023
        int d = l >> 4, o = (l & 15) * 8;
        *(uint4*)&CtT[(size_t)d * JP + i0 + o] = *(uint4*)&T[d * 136 + o];
    }
}

__global__ void __launch_bounds__(256) gemm1_kernel(const float* __restrict__ x,
                                                    const float* __restrict__ W1) {
    int h = blockIdx.y;
    gemm_tf32_body<HID>(x, W1 + (size_t)h * F_IN * HID,
                        g_Wh + (size_t)h * N_NODES * HID,
                        g_WhT + (size_t)h * HID * JP,
                        blockIdx.x * 128);
}

__global__ void __launch_bounds__(256) gemm2_kernel(const float* __restrict__ W2) {
    gemm_tf32_body<C_OUT>(g_h1, W2, g_Wh2, g_WhT2, blockIdx.x * 128);
}

// ---------------- kernel 3: per-node scores + packed {e,f} tables (layer 1) ----------------
__global__ void scores1_kernel(const float* __restrict__ a_src,
                               const float* __restrict__ a_tgt) {
    int gw = (blockIdx.x * blockDim.x + threadIdx.x) >> 5;
    int lane = threadIdx.x & 31;
    if (gw >= H1 * N_NODES) return;
    int h = gw / N_NODES, n = gw % N_NODES;
    const float* wh = &g_Wh[((size_t)h * N_NODES + n) * HID];
    float w1 = wh[lane], w2 = wh[lane + 32];
    float ss = w1 * a_src[h * HID + lane] + w2 * a_src[h * HID + lane + 32];
    float st = w1 * a_tgt[h * HID + lane] + w2 * a_tgt[h * HID + lane + 32];
    #pragma unroll
    for (int o = 16; o > 0; o >>= 1) {
        ss += __shfl_xor_sync(0xFFFFFFFFu, ss, o);
        st += __shfl_xor_sync(0xFFFFFFFFu, st, o);
    }
    if (lane == 0) {
        g_Ei[gw] = expf(ss); g_Fi[gw] = expf(ALPHA * ss);
        __half* pk = (__half*)&g_pk1[(size_t)h * (JP / 2) + (n >> 1)];
        int o = n & 1;
        pk[0 + o] = __float2half_rn(expf(st));
        pk[2 + o] = __float2half_rn(expf(ALPHA * st));
    }
}

// ---------------- fused masked-softmax AV on mma.sync ----------------
// 128 threads = 4 warps, 32 rows/warp (2 row-groups) -> 128 rows/block.
// w = mask * max(Ei*ej, Fi*fj). Adjacency words now flow through the cp.async
// pipeline (8B per thread per tile) -> LDS.64 broadcast instead of exposed LDG.
template<int NG, int NGL, bool L2K>
__global__ void __launch_bounds__(128, 4) av_mma_kernel(float* __restrict__ dummy) {
    __shared__ __align__(16) __half Bbuf[3][64 * 72];
    __shared__ __align__(16) uint2  Pbuf[3][32];
    __shared__ __align__(16) uint2  Abuf[3][128];

    int tid = threadIdx.x;
    int lane = tid & 31, warp = tid >> 5;
    int i0 = blockIdx.x * 128;

    const float *Eiv, *Fiv;
    const uint2* pk;
    const __half* whT;
    int tbeg, NT, pidx, zcol;
    if (L2K) {
        Eiv = g_E2i; Fiv = g_F2i;
        pk = g_pk2; whT = g_WhT2;
        int y = blockIdx.y;
        tbeg = (y < 6) ? y * 12 : 72 + (y - 6) * 11;
        NT   = (y < 6) ? 12 : 11;
        pidx = y; zcol = 40;
    } else {
        int h = blockIdx.y;
        int hb = h * N_NODES;
        Eiv = g_Ei + hb; Fiv = g_Fi + hb;
        pk = g_pk1 + (size_t)h * (JP / 2);
        whT = g_WhT + (size_t)h * HID * JP;
        int z = blockIdx.z;                    // 3-way j split: 32,31,31
        tbeg = (z == 0) ? 0 : 32 + (z - 1) * 31;
        NT   = (z == 0) ? 32 : 31;
        pidx = h * 3 + z; zcol = 64;
    }

    // 4 row slots: r0 + {0,8,16,24}
    int r0 = i0 + warp * 32 + (lane >> 2);
    __half2 E2[4], F2[4];
    #pragma unroll
    for (int s = 0; s < 4; s++) {
        int rc = min(r0 + s * 8, N_NODES - 1);
        E2[s] = __half2half2(__float2half_rn(Eiv[rc]));
        F2[s] = __half2half2(__float2half_rn(Fiv[rc]));
    }
    int c4 = lane & 3, cb = c4 * 2;

    // adjacency staging: thread tid owns row i0+tid (clamped)
    const unsigned* adj_mine = &g_adjb[(size_t)min(i0 + tid, N_NODES - 1) * NW];
    int aidx = warp * 32 + (lane >> 2);        // base row index within block

    int nb = (lane & 7) | (((lane >> 4) & 1) << 3);
    int kb = ((lane >> 3) & 1) * 8;
    uint32_t bB[3] = { smem_u32(Bbuf[0]), smem_u32(Bbuf[1]), smem_u32(Bbuf[2]) };
    uint32_t lds_off = (uint32_t)(nb * 72 + kb) * 2;

    float acc[2][NG][4];
    float accz[2][4];
    #pragma unroll
    for (int g = 0; g < 2; g++) {
        #pragma unroll
        for (int n = 0; n < NG; n++)
            #pragma unroll
            for (int c = 0; c < 4; c++) acc[g][n][c] = 0.f;
        #pragma unroll
        for (int c = 0; c < 4; c++) accz[g][c] = 0.f;
    }

    const uint32_t ONES2 = 0x3C003C00u;
    const uint32_t bz[2] = { ONES2, ONES2 };

    auto stage = [&](int t, int b) {
        int j0 = (tbeg + t) * 64;
        #pragma unroll
        for (int i2 = 0; i2 < 4; i2++) {
            int c = tid + 128 * i2;
            int n = c >> 3, o = c & 7;
            CP_ASYNC16(bB[b] + (uint32_t)(n * 144 + o * 16),
                       whT + (size_t)n * JP + j0 + o * 8);
        }
        // adjacency uint2 for my row, this tile (8B aligned: NW even, 2t even)
        CP_ASYNC8(smem_u32(&Abuf[b][tid]), adj_mine + 2 * (tbeg + t));
        if (tid >= 96 && tid < 112) {
            int e = tid - 96;                  // 0..15, 2 uint2 entries each
            CP_ASYNC16(smem_u32(&Pbuf[b][e * 2]), pk + (j0 >> 1) + e * 2);
        }
    };

    stage(0, 0); CP_COMMIT();
    if (NT > 1) { stage(1, 1); CP_COMMIT(); }

    for (int t = 0; t < NT; t++) {
        int b = t % 3;
        if (t + 1 < NT) CP_WAIT1(); else CP_WAIT0();
        __syncthreads();
        if (t + 2 < NT) { stage(t + 2, (t + 2) % 3); CP_COMMIT(); }

        // adjacency words from smem (broadcast LDS.64, conflict-free)
        uint2 aw[4];
        #pragma unroll
        for (int s = 0; s < 4; s++)
            aw[s] = Abuf[b][aidx + s * 8];

        #pragma unroll
        for (int ks = 0; ks < 4; ks++) {
            uint2 p0 = Pbuf[b][ks * 8 + c4];
            uint2 p1 = Pbuf[b][ks * 8 + c4 + 4];
            __half2 eA = *(__half2*)&p0.x, fA = *(__half2*)&p0.y;
            __half2 eB = *(__half2*)&p1.x, fB = *(__half2*)&p1.y;

            int sh = ((ks & 1) << 4) + cb;
            // build A fragments for BOTH row groups first (8 regs)
            uint32_t a2[2][4];
            #pragma unroll
            for (int g = 0; g < 2; g++) {
                #pragma unroll
                for (int rr = 0; rr < 2; rr++) {
                    int s = g * 2 + rr;
                    unsigned word = (ks < 2) ? aw[s].x : aw[s].y;
                    unsigned ta = word >> sh;
                    unsigned tb2 = ta >> 8;
                    uint32_t ma = (ta  & 1u) * 0x3C00u + (ta  & 2u) * 0x1E000000u;
                    uint32_t mb = (tb2 & 1u) * 0x3C00u + (tb2 & 2u) * 0x1E000000u;

                    __half2 wa = __hmul2(
                        __hmax2(__hmul2(E2[s], eA), __hmul2(F2[s], fA)), *(__half2*)&ma);
                    __half2 wbv = __hmul2(
                        __hmax2(__hmul2(E2[s], eB), __hmul2(F2[s], fB)), *(__half2*)&mb);

                    a2[g][rr]     = *(uint32_t*)&wa;
                    a2[g][rr + 2] = *(uint32_t*)&wbv;
                }
            }
            // consume B fragments 4 regs at a time
            #pragma unroll
            for (int p = 0; p < NGL / 2; p++) {
                uint32_t bf0[2], bf1[2];
                ldsm_x4(bf0[0], bf0[1], bf1[0], bf1[1],
                        bB[b] + lds_off + (uint32_t)(p * 16 * 144 + ks * 32));
                int n0 = 2 * p, n1 = 2 * p + 1;
                if (n0 < NG) { mma_16816(acc[0][n0], a2[0], bf0); mma_16816(acc[1][n0], a2[1], bf0); }
                if (n1 < NG) { mma_16816(acc[0][n1], a2[0], bf1); mma_16816(acc[1][n1], a2[1], bf1); }
            }
            mma_16816(accz[0], a2[0], bz);
            mma_16816(accz[1], a2[1], bz);
        }
    }

    // ---- epilogue: partial store (D cols + Z) ----
    #pragma unroll
    for (int g = 0; g < 2; g++) {
        #pragma unroll
        for (int rr = 0; rr < 2; rr++) {
            int row = r0 + (g * 2 + rr) * 8;
            if (row >= N_NODES) continue;
            size_t base = ((size_t)pidx * 6016 + row) * 72;
            #pragma unroll
            for (int n = 0; n < NG; n++)
                *(float2*)&g_part[base + n * 8 + cb] =
                    make_float2(acc[g][n][rr * 2], acc[g][n][rr * 2 + 1]);
            if (cb == 0) g_part[base + zcol] = accz[g][rr * 2];
        }
    }
}

// ---------------- layer-1 combine (3 parts per head): normalize + ELU -> g_h1 ----------------
__global__ void combine1_kernel() {
    int idx = blockIdx.x * blockDim.x + threadIdx.x;   // over H1*N_NODES*32 float2 units
    if (idx >= H1 * N_NODES * 32) return;
    int c2 = idx & 31;
    int rest = idx >> 5;
    int row = rest % N_NODES;
    int h = rest / N_NODES;
    float na = 0.f, nb2 = 0.f, z = 0.f;
    #pragma unroll
    for (int k = 0; k < 3; k++) {
        size_t b = ((size_t)(h * 3 + k) * 6016 + row) * 72;
        float2 v = *(float2*)&g_part[b + c2 * 2];
        na += v.x; nb2 += v.y;
        z += g_part[b + 64];
    }
    float invZ = 1.0f / z;
    float a = na * invZ, b = nb2 * invZ;
    a = a > 0.f ? a : expm1f(a);
    b = b > 0.f ? b : expm1f(b);
    *(float2*)&g_h1[(size_t)row * (H1 * HID) + h * HID + c2 * 2] = make_float2(a, b);
}

// ---------------- layer-2 partial combine (8 parts) ----------------
__global__ void combine2_kernel(float* __restrict__ out) {
    int idx = blockIdx.x * blockDim.x + threadIdx.x;
    if (idx >= N_NODES * C_OUT) return;
    int row = idx / C_OUT, c = idx - row * C_OUT;
    float num = 0.f, z = 0.f;
    #pragma unroll
    for (int y = 0; y < 8; y++) {
        size_t b = ((size_t)y * 6016 + row) * 72;
        num += g_part[b + c];
        z   += g_part[b + 40];
    }
    out[idx] = num / z;
}

// ---------------- kernel 6: layer-2 scores (packed {e,f} table) ----------------
__global__ void scores2_kernel(const float* __restrict__ a_src2,
                               const float* __restrict__ a_tgt2) {
    int gw = (blockIdx.x * blockDim.x + threadIdx.x) >> 5;
    int lane = threadIdx.x & 31;
    if (gw >= N_NODES) return;
    float w1 = g_Wh2[(size_t)gw * C_OUT + lane];
    float as1 = a_src2[lane], at1 = a_tgt2[lane];
    float w2 = 0.f, as2 = 0.f, at2 = 0.f;
    if (lane + 32 < C_OUT) {
        w2 = g_Wh2[(size_t)gw * C_OUT + lane + 32];
        as2 = a_src2[lane + 32]; at2 = a_tgt2[lane + 32];
    }
    float ss = w1 * as1 + w2 * as2;
    float st = w1 * at1 + w2 * at2;
    #pragma unroll
    for (int o = 16; o > 0; o >>= 1) {
        ss += __shfl_xor_sync(0xFFFFFFFFu, ss, o);
        st += __shfl_xor_sync(0xFFFFFFFFu, st, o);
    }
    if (lane == 0) {
        g_E2i[gw] = expf(ss); g_F2i[gw] = expf(ALPHA * ss);
        __half* pkw = (__half*)&g_pk2[gw >> 1];
        int o = gw & 1;
        pkw[0 + o] = __float2half_rn(expf(st));
        pkw[2 + o] = __float2half_rn(expf(ALPHA * st));
    }
}

// ---------------- launch ----------------
extern "C" void kernel_launch(void* const* d_in, const int* in_sizes, int n_in,
                              void* d_out, int out_size) {
    const float* x      = (const float*)d_in[0];
    const int*   adj    = (const int*)  d_in[1];
    const float* W1     = (const float*)d_in[2];
    const float* a_src1 = (const float*)d_in[3];
    const float* a_tgt1 = (const float*)d_in[4];
    const float* W2     = (const float*)d_in[5];
    const float* a_src2 = (const float*)d_in[6];
    const float* a_tgt2 = (const float*)d_in[7];
    float* out = (float*)d_out;

    pack_adj_kernel<<<(N_NODES * NW * 32) / 256, 256>>>(adj, out, (long)out_size);

    gemm1_kernel<<<dim3((N_NODES + 127) / 128, H1), 256>>>(x, W1);
    scores1_kernel<<<(H1 * N_NODES * 32 + 255) / 256, 256>>>(a_src1, a_tgt1);
    av_mma_kernel<8, 8, false><<<dim3(JP / 128, H1, 3), 128>>>(nullptr);
    combine1_kernel<<<(H1 * N_NODES * 32 + 255) / 256, 256>>>();

    gemm2_kernel<<<(N_NODES + 127) / 128, 256>>>(W2);
    scores2_kernel<<<(N_NODES * 32 + 255) / 256, 256>>>(a_src2, a_tgt2);
    av_mma_kernel<5, 6, true><<<dim3(JP / 128, 8), 128>>>(nullptr);
    combine2_kernel<<<(N_NODES * C_OUT + 255) / 256, 256>>>(out);
}

// round 16
// speedup vs baseline: 1.2192x; 1.0107x over previous
#include <cuda_runtime.h>
#include <cuda_fp16.h>
#include <math.h>
#include <stdint.h>

// ---------------- problem constants ----------------
#define N_NODES 6000
#define JP      6016           // N padded to multiple of 64
#define F_IN    512
#define HID     64
#define H1      8
#define C_OUT   40
#define NW      188
#define ALPHA   0.2f
#define OUT_ADJ_OFF (N_NODES * C_OUT)
#define NT_FULL 94             // JP/64

// ---------------- device scratch ----------------
__device__ __half   g_WhT [H1 * HID * (size_t)JP];
__device__ unsigned g_adjb[N_NODES * NW];
__device__ float    g_h1  [N_NODES * (H1 * HID)];
__device__ __half   g_WhT2[HID * (size_t)JP];
__device__ float    g_part[24 * 6016 * 72];      // partials: stride 72; L1 Z@64, L2 Z@40

__device__ float  g_Ei[H1 * N_NODES], g_Fi[H1 * N_NODES];
__device__ float  g_E2i[N_NODES], g_F2i[N_NODES];
// packed per-j tables: entry (j/2) = { e2, f2 } halves; zero in pad region
__device__ uint2  g_pk1[H1 * (JP / 2)];
__device__ uint2  g_pk2[JP / 2];

// ---------------- helpers ----------------
__device__ __forceinline__ uint32_t smem_u32(const void* p) {
    uint32_t a;
    asm("{ .reg .u64 t; cvta.to.shared.u64 t, %1; cvt.u32.u64 %0, t; }" : "=r"(a) : "l"(p));
    return a;
}
__device__ __forceinline__ void mma_16816(float c[4], const uint32_t a[4], const uint32_t b[2]) {
    asm volatile(
        "mma.sync.aligned.m16n8k16.row.col.f32.f16.f16.f32 "
        "{%0,%1,%2,%3}, {%4,%5,%6,%7}, {%8,%9}, {%0,%1,%2,%3};"
        : "+f"(c[0]), "+f"(c[1]), "+f"(c[2]), "+f"(c[3])
        : "r"(a[0]), "r"(a[1]), "r"(a[2]), "r"(a[3]), "r"(b[0]), "r"(b[1]));
}
__device__ __forceinline__ void mma_tf32(float c[4], const uint32_t a[4], const uint32_t b[2]) {
    asm volatile(
        "mma.sync.aligned.m16n8k8.row.col.f32.tf32.tf32.f32 "
        "{%0,%1,%2,%3}, {%4,%5,%6,%7}, {%8,%9}, {%0,%1,%2,%3};"
        : "+f"(c[0]), "+f"(c[1]), "+f"(c[2]), "+f"(c[3])
        : "r"(a[0]), "r"(a[1]), "r"(a[2]), "r"(a[3]), "r"(b[0]), "r"(b[1]));
}
__device__ __forceinline__ void ldsm_x4(uint32_t& r0, uint32_t& r1, uint32_t& r2, uint32_t& r3,
                                        uint32_t addr) {
    asm volatile("ldmatrix.sync.aligned.m8n8.x4.shared.b16 {%0,%1,%2,%3}, [%4];"
                 : "=r"(r0), "=r"(r1), "=r"(r2), "=r"(r3) : "r"(addr));
}
__device__ __forceinline__ uint32_t tf32_of(float x) {
    uint32_t r;
    asm("cvt.rna.tf32.f32 %0, %1;" : "=r"(r) : "f"(x));
    return r;
}
#define CP_ASYNC16(dst, src) \
    asm volatile("cp.async.cg.shared.global [%0], [%1], 16;" :: "r"(dst), "l"(src))
#define CP_ASYNC8(dst, src) \
    asm volatile("cp.async.ca.shared.global [%0], [%1], 8;" :: "r"(dst), "l"(src))
#define CP_COMMIT() asm volatile("cp.async.commit_group;" ::: "memory")
#define CP_WAIT1()  asm volatile("cp.async.wait_group 1;" ::: "memory")
#define CP_WAIT0()  asm volatile("cp.async.wait_group 0;" ::: "memory")

// ---------------- kernel 1: pack adjacency + echo adj to output ----------------
__global__ void pack_adj_kernel(const int* __restrict__ adj,
                                float* __restrict__ outf, long out_size) {
    int gtid = blockIdx.x * blockDim.x + threadIdx.x;
    int warp = gtid >> 5, lane = gtid & 31;
    int row = warp / NW, wj = warp % NW;
    int j = wj * 32 + lane;
    int v = 0;
    if (j < N_NODES) {
        long idx = (long)row * N_NODES + j;
        v = adj[idx];
        long oi = (long)OUT_ADJ_OFF + idx;
        if (oi < out_size) outf[oi] = (float)v;
    }
    unsigned bits = __ballot_sync(0xFFFFFFFFu, v != 0);
    if (lane == 0) g_adjb[row * NW + wj] = bits;
}

// ---------------- tf32 GEMM + fused score epilogue (256 threads) ----------------
// Computes C[128 x NB] = A[128 x 512] * B, emits fp16 transposed C AND the
// per-row attention scores (Ei/Fi + packed {e,f} j-table) directly from the
// fp16 transpose buffer. No fp32 C output needed.
template<int NB>
__device__ __forceinline__ void gemm_tf32_body(
    const float* __restrict__ Asrc,
    const float* __restrict__ Bsrc,
    __half* __restrict__ CtT,
    int i0,
    const float* __restrict__ a_src,
    const float* __restrict__ a_tgt,
    float* __restrict__ Ev, float* __restrict__ Fv,
    uint2* __restrict__ pkv)
{
    __shared__ __align__(16) char sbuf[17408];
    float* As = (float*)sbuf;                 // [128][20]
    float* Bs = (float*)(sbuf + 10240);       // [16][72]
    __half* T = (__half*)sbuf;                // [64][136] reused after mainloop

    int tid = threadIdx.x;
    int lane = tid & 31, warp = tid >> 5;
    int wr = warp >> 1, wc = warp & 1;

    float acc[2][4][4];
    #pragma unroll
    for (int m = 0; m < 2; m++)
        #pragma unroll
        for (int n = 0; n < 4; n++)
            #pragma unroll
            for (int c = 0; c < 4; c++) acc[m][n][c] = 0.f;

    int sr = tid >> 1, skk = (tid & 1) * 8;
    int bkk = tid >> 4, bn0 = (tid & 15) * 4;

    for (int k0 = 0; k0 < F_IN; k0 += 16) {
        {
            float4 v0 = make_float4(0.f, 0.f, 0.f, 0.f), v1 = v0;
            if (i0 + sr < N_NODES) {
                const float* src = &Asrc[(size_t)(i0 + sr) * F_IN + k0 + skk];
                v0 = *(const float4*)src;
                v1 = *(const float4*)(src + 4);
            }
            uint32_t* d = (uint32_t*)&As[sr * 20 + skk];
            d[0] = tf32_of(v0.x); d[1] = tf32_of(v0.y); d[2] = tf32_of(v0.z); d[3] = tf32_of(v0.w);
            d[4] = tf32_of(v1.x); d[5] = tf32_of(v1.y); d[6] = tf32_of(v1.z); d[7] = tf32_of(v1.w);
        }
        {
            float4 b = make_float4(0.f, 0.f, 0.f, 0.f);
            if (bn0 < NB)
                b = *(const float4*)&Bsrc[(size_t)(k0 + bkk) * NB + bn0];
            uint32_t* d = (uint32_t*)&Bs[bkk * 72 + bn0];
            d[0] = tf32_of(b.x); d[1] = tf32_of(b.y); d[2] = tf32_of(b.z); d[3] = tf32_of(b.w);
        }
        __syncthreads();

        #pragma unroll
        for (int s = 0; s < 2; s++) {
            int arow = wr * 32 + (lane >> 2);
            int akol = s * 8 + (lane & 3);
            uint32_t af[2][4];
            #pragma unroll
            for (int m = 0; m < 2; m++) {
                int base = (arow + m * 16) * 20 + akol;
                af[m][0] = __float_as_uint(As[base]);
                af[m][1] = __float_as_uint(As[base + 8 * 20]);
                af[m][2] = __float_as_uint(As[base + 4]);
                af[m][3] = __float_as_uint(As[base + 8 * 20 + 4]);
            }
            int bb = (s * 8 + (lane & 3)) * 72 + wc * 32 + (lane >> 2);
            uint32_t bf[4][2];
            #pragma unroll
            for (int n = 0; n < 4; n++) {
                bf[n][0] = __float_as_uint(Bs[bb + n * 8]);
                bf[n][1] = __float_as_uint(Bs[bb + n * 8 + 4 * 72]);
            }
            #pragma unroll
            for (int m = 0; m < 2; m++)
                #pragma unroll
                for (int n = 0; n < 4; n++)
                    mma_tf32(acc[m][n], af[m], bf[n]);
        }
        __syncthreads();
    }

    // fp16 transpose into smem
    int rl = wr * 32 + (lane >> 2);
    int cbx = wc * 32 + (lane & 3) * 2;
    #pragma unroll
    for (int m = 0; m < 2; m++) {
        int r0 = rl + m * 16, r1 = r0 + 8;
        #pragma unroll
        for (int n = 0; n < 4; n++) {
            int c = cbx + n * 8;
            T[(c + 0) * 136 + r0] = __float2half_rn(acc[m][n][0]);
            T[(c + 1) * 136 + r0] = __float2half_rn(acc[m][n][1]);
            T[(c + 0) * 136 + r1] = __float2half_rn(acc[m][n][2]);
            T[(c + 1) * 136 + r1] = __float2half_rn(acc[m][n][3]);
        }
    }
    __syncthreads();

    // global fp16 transposed writeback
    #pragma unroll
    for (int q = 0; q < 4; q++) {
        int l = tid + 256 * q;               // 0..1023
        int d = l >> 4, o = (l & 15) * 8;
        *(uint4*)&CtT[(size_t)d * JP + i0 + o] = *(uint4*)&T[d * 136 + o];
    }

    // ---- fused scores: 2 threads per row, each sums 32 cols from T ----
    {
        int row_l = tid >> 1, hv = tid & 1;
        float ss = 0.f, st = 0.f;
        #pragma unroll 8
        for (int c = hv * 32; c < hv * 32 + 32; c++) {
            if (c < NB) {
                float w = __half2float(T[c * 136 + row_l]);
                ss += w * __ldg(&a_src[c]);
                st += w * __ldg(&a_tgt[c]);
            }
        }
        ss += __shfl_xor_sync(0xFFFFFFFFu, ss, 1);
        st += __shfl_xor_sync(0xFFFFFFFFu, st, 1);
        int row_g = i0 + row_l;
        if (hv == 0 && row_g < N_NODES) {
            Ev[row_g] = expf(ss);
            Fv[row_g] = expf(ALPHA * ss);
            __half* pw = (__half*)&pkv[row_g >> 1];
            int o = row_g & 1;
            pw[0 + o] = __float2half_rn(expf(st));
            pw[2 + o] = __float2half_rn(expf(ALPHA * st));
        }
    }
}

__global__ void __launch_bounds__(256) gemm1_kernel(const float* __restrict__ x,
                                                    const float* __restrict__ W1,
                                                    const float* __restrict__ a_src,
                                                    const float* __restrict__ a_tgt) {
    int h = blockIdx.y;
    gemm_tf32_body<HID>(x, W1 + (size_t)h * F_IN * HID,
                        g_WhT + (size_t)h * HID * JP,
                        blockIdx.x * 128,
                        a_src + h * HID, a_tgt + h * HID,
                        g_Ei + h * N_NODES, g_Fi + h * N_NODES,
                        g_pk1 + (size_t)h * (JP / 2));
}

__global__ void __launch_bounds__(256) gemm2_kernel(const float* __restrict__ W2,
                                                    const float* __restrict__ a_src2,
                                                    const float* __restrict__ a_tgt2) {
    gemm_tf32_body<C_OUT>(g_h1, W2, g_WhT2, blockIdx.x * 128,
                          a_src2, a_tgt2, g_E2i, g_F2i, g_pk2);
}

// ---------------- fused masked-softmax AV on mma.sync ----------------
// 128 threads = 4 warps, 32 rows/warp (2 row-groups) -> 128 rows/block.
// w = mask * max(Ei*ej, Fi*fj). Adjacency + scalars through cp.async pipeline.
template<int NG, int NGL, bool L2K>
__global__ void __launch_bounds__(128, 4) av_mma_kernel(float* __restrict__ dummy) {
    __shared__ __align__(16) __half Bbuf[3][64 * 72];
    __shared__ __align__(16) uint2  Pbuf[3][32];
    __shared__ __align__(16) uint2  Abuf[3][128];

    int tid = threadIdx.x;
    int lane = tid & 31, warp = tid >> 5;
    int i0 = blockIdx.x * 128;

    const float *Eiv, *Fiv;
    const uint2* pk;
    const __half* whT;
    int tbeg, NT, pidx, zcol;
    if (L2K) {
        Eiv = g_E2i; Fiv = g_F2i;
        pk = g_pk2; whT = g_WhT2;
        int y = blockIdx.y;                    // 12-way split: 10x8 + 2x7 = 94
        tbeg = (y < 10) ? y * 8 : 80 + (y - 10) * 7;
        NT   = (y < 10) ? 8 : 7;
        pidx = y; zcol = 40;
    } else {
        int h = blockIdx.y;
        int hb = h * N_NODES;
        Eiv = g_Ei + hb; Fiv = g_Fi + hb;
        pk = g_pk1 + (size_t)h * (JP / 2);
        whT = g_WhT + (size_t)h * HID * JP;
        int z = blockIdx.z;                    // 3-way j split: 32,31,31
        tbeg = (z == 0) ? 0 : 32 + (z - 1) * 31;
        NT   = (z == 0) ? 32 : 31;
        pidx = h * 3 + z; zcol = 64;
    }

    // 4 row slots: r0 + {0,8,16,24}
    int r0 = i0 + warp * 32 + (lane >> 2);
    __half2 E2[4], F2[4];
    #pragma unroll
    for (int s = 0; s < 4; s++) {
        int rc = min(r0 + s * 8, N_NODES - 1);
        E2[s] = __half2half2(__float2half_rn(Eiv[rc]));
        F2[s] = __half2half2(__float2half_rn(Fiv[rc]));
    }
    int c4 = lane & 3, cb = c4 * 2;

    const unsigned* adj_mine = &g_adjb[(size_t)min(i0 + tid, N_NODES - 1) * NW];
    int aidx = warp * 32 + (lane >> 2);

    int nb = (lane & 7) | (((lane >> 4) & 1) << 3);
    int kb = ((lane >> 3) & 1) * 8;
    uint32_t bB[3] = { smem_u32(Bbuf[0]), smem_u32(Bbuf[1]), smem_u32(Bbuf[2]) };
    uint32_t lds_off = (uint32_t)(nb * 72 + kb) * 2;

    float acc[2][NG][4];
    float accz[2][4];
    #pragma unroll
    for (int g = 0; g < 2; g++) {
        #pragma unroll
        for (int n = 0; n < NG; n++)
            #pragma unroll
            for (int c = 0; c < 4; c++) acc[g][n][c] = 0.f;
        #pragma unroll
        for (int c = 0; c < 4; c++) accz[g][c] = 0.f;
    }

    const uint32_t ONES2 = 0x3C003C00u;
    const uint32_t bz[2] = { ONES2, ONES2 };

    auto stage = [&](int t, int b) {
        int j0 = (tbeg + t) * 64;
        #pragma unroll
        for (int i2 = 0; i2 < 4; i2++) {
            int c = tid + 128 * i2;
            int n = c >> 3, o = c & 7;
            CP_ASYNC16(bB[b] + (uint32_t)(n * 144 + o * 16),
                       whT + (size_t)n * JP + j0 + o * 8);
        }
        CP_ASYNC8(smem_u32(&Abuf[b][tid]), adj_mine + 2 * (tbeg + t));
        if (tid >= 96 && tid < 112) {
            int e = tid - 96;
            CP_ASYNC16(smem_u32(&Pbuf[b][e * 2]), pk + (j0 >> 1) + e * 2);
        }
    };

    stage(0, 0); CP_COMMIT();
    if (NT > 1) { stage(1, 1); CP_COMMIT(); }

    for (int t = 0; t < NT; t++) {
        int b = t % 3;
        if (t + 1 < NT) CP_WAIT1(); else CP_WAIT0();
        __syncthreads();
        if (t + 2 < NT) { stage(t + 2, (t + 2) % 3); CP_COMMIT(); }

        uint2 aw[4];
        #pragma unroll
        for (int s = 0; s < 4; s++)
            aw[s] = Abuf[b][aidx + s * 8];

        #pragma unroll
        for (int ks = 0; ks < 4; ks++) {
            uint2 p0 = Pbuf[b][ks * 8 + c4];
            uint2 p1 = Pbuf[b][ks * 8 + c4 + 4];
            __half2 eA = *(__half2*)&p0.x, fA = *(__half2*)&p0.y;
            __half2 eB = *(__half2*)&p1.x, fB = *(__half2*)&p1.y;

            int sh = ((ks & 1) << 4) + cb;
            uint32_t a2[2][4];
            #pragma unroll
            for (int g = 0; g < 2; g++) {
                #pragma unroll
                for (int rr = 0; rr < 2; rr++) {
                    int s = g * 2 + rr;
                    unsigned word = (ks < 2) ? aw[s].x : aw[s].y;
                    unsigned ta = word >> sh;
                    unsigned tb2 = ta >> 8;
                    uint32_t ma = (ta  & 1u) * 0x3C00u + (ta  & 2u) * 0x1E000000u;
                    uint32_t mb = (tb2 & 1u) * 0x3C00u + (tb2 & 2u) * 0x1E000000u;

                    __half2 wa = __hmul2(
                        __hmax2(__hmul2(E2[s], eA), __hmul2(F2[s], fA)), *(__half2*)&ma);
                    __half2 wbv = __hmul2(
                        __hmax2(__hmul2(E2[s], eB), __hmul2(F2[s], fB)), *(__half2*)&mb);

                    a2[g][rr]     = *(uint32_t*)&wa;
                    a2[g][rr + 2] = *(uint32_t*)&wbv;
                }
            }
            #pragma unroll
            for (int p = 0; p < NGL / 2; p++) {
                uint32_t bf0[2], bf1[2];
                ldsm_x4(bf0[0], bf0[1], bf1[0], bf1[1],
                        bB[b] + lds_off + (uint32_t)(p * 16 * 144 + ks * 32));
                int n0 = 2 * p, n1 = 2 * p + 1;
                if (n0 < NG) { mma_16816(acc[0][n0], a2[0], bf0); mma_16816(acc[1][n0], a2[1], bf0); }
                if (n1 < NG) { mma_16816(acc[0][n1], a2[0], bf1); mma_16816(acc[1][n1], a2[1], bf1); }
            }
            mma_16816(accz[0], a2[0], bz);
            mma_16816(accz[1], a2[1], bz);
        }
    }

    // ---- epilogue: partial store (D cols + Z) ----
    #pragma unroll
    for (int g = 0; g < 2; g++) {
        #pragma unroll
        for (int rr = 0; rr < 2; rr++) {
            int row = r0 + (g * 2 + rr) * 8;
            if (row >= N_NODES) continue;
            size_t base = ((size_t)pidx * 6016 + row) * 72;
            #pragma unroll
            for (int n = 0; n < NG; n++)
                *(float2*)&g_part[base + n * 8 + cb] =
                    make_float2(acc[g][n][rr * 2], acc[g][n][rr * 2 + 1]);
            if (cb == 0) g_part[base + zcol] = accz[g][rr * 2];
        }
    }
}

// ---------------- layer-1 combine (3 parts per head): normalize + ELU -> g_h1 ----------------
__global__ void combine1_kernel() {
    int idx = blockIdx.x * blockDim.x + threadIdx.x;
    if (idx >= H1 * N_NODES * 32) return;
    int c2 = idx & 31;
    int rest = idx >> 5;
    int row = rest % N_NODES;
    int h = rest / N_NODES;
    float na = 0.f, nb2 = 0.f, z = 0.f;
    #pragma unroll
    for (int k = 0; k < 3; k++) {
        size_t b = ((size_t)(h * 3 + k) * 6016 + row) * 72;
        float2 v = *(float2*)&g_part[b + c2 * 2];
        na += v.x; nb2 += v.y;
        z += g_part[b + 64];
    }
    float invZ = 1.0f / z;
    float a = na * invZ, b = nb2 * invZ;
    a = a > 0.f ? a : expm1f(a);
    b = b > 0.f ? b : expm1f(b);
    *(float2*)&g_h1[(size_t)row * (H1 * HID) + h * HID + c2 * 2] = make_float2(a, b);
}

// ---------------- layer-2 partial combine (12 parts) ----------------
__global__ void combine2_kernel(float* __restrict__ out) {
    int idx = blockIdx.x * blockDim.x + threadIdx.x;
    if (idx >= N_NODES * C_OUT) return;
    int row = idx / C_OUT, c = idx - row * C_OUT;
    float num = 0.f, z = 0.f;
    #pragma unroll
    for (int y = 0; y < 12; y++) {
        size_t b = ((size_t)y * 6016 + row) * 72;
        num += g_part[b + c];
        z   += g_part[b + 40];
    }
    out[idx] = num / z;
}

// ---------------- launch ----------------
extern "C" void kernel_launch(void* const* d_in, const int* in_sizes, int n_in,
                              void* d_out, int out_size) {
    const float* x      = (const float*)d_in[0];
    const int*   adj    = (const int*)  d_in[1];
    const float* W1     = (const float*)d_in[2];
    const float* a_src1 = (const float*)d_in[3];
    const float* a_tgt1 = (const float*)d_in[4];
    const float* W2     = (const float*)d_in[5];
    const float* a_src2 = (const float*)d_in[6];
    const float* a_tgt2 = (const float*)d_in[7];
    float* out = (float*)d_out;

    pack_adj_kernel<<<(N_NODES * NW * 32) / 256, 256>>>(adj, out, (long)out_size);

    gemm1_kernel<<<dim3((N_NODES + 127) / 128, H1), 256>>>(x, W1, a_src1, a_tgt1);
    av_mma_kernel<8, 8, false><<<dim3(JP / 128, H1, 3), 128>>>(nullptr);
    combine1_kernel<<<(H1 * N_NODES * 32 + 255) / 256, 256>>>();

    gemm2_kernel<<<(N_NODES + 127) / 128, 256>>>(W2, a_src2, a_tgt2);
    av_mma_kernel<5, 6, true><<<dim3(JP / 128, 12), 128>>>(nullptr);
    combine2_kernel<<<(N_NODES * C_OUT + 255) / 256, 256>>>(out);
}

// round 17
// speedup vs baseline: 1.2592x; 1.0328x over previous
#include <cuda_runtime.h>
#include <cuda_fp16.h>
#include <math.h>
#include <stdint.h>

// ---------------- problem constants ----------------
#define N_NODES 6000
#define JP      6016           // N padded to multiple of 64
#define F_IN    512
#define HID     64
#define H1      8
#define C_OUT   40
#define NW      188
#define ALPHA   0.2f
#define OUT_ADJ_OFF (N_NODES * C_OUT)
#define NT_FULL 94             // JP/64

// ---------------- device scratch ----------------
__device__ __half   g_WhT [H1 * HID * (size_t)JP];
__device__ unsigned g_adjb[N_NODES * NW];
__device__ float    g_h1  [N_NODES * (H1 * HID)];
__device__ __half   g_WhT2[HID * (size_t)JP];
__device__ float    g_part[24 * 6016 * 72];      // partials: stride 72; L1 Z@64, L2 Z@40

__device__ float  g_Ei[H1 * N_NODES], g_Fi[H1 * N_NODES];
__device__ float  g_E2i[N_NODES], g_F2i[N_NODES];
// packed per-j tables: entry (j/2) = { e2, f2 } halves; zero in pad region
__device__ uint2  g_pk1[H1 * (JP / 2)];
__device__ uint2  g_pk2[JP / 2];

// ---------------- helpers ----------------
__device__ __forceinline__ uint32_t smem_u32(const void* p) {
    uint32_t a;
    asm("{ .reg .u64 t; cvta.to.shared.u64 t, %1; cvt.u32.u64 %0, t; }" : "=r"(a) : "l"(p));
    return a;
}
__device__ __forceinline__ void mma_16816(float c[4], const uint32_t a[4], const uint32_t b[2]) {
    asm volatile(
        "mma.sync.aligned.m16n8k16.row.col.f32.f16.f16.f32 "
        "{%0,%1,%2,%3}, {%4,%5,%6,%7}, {%8,%9}, {%0,%1,%2,%3};"
        : "+f"(c[0]), "+f"(c[1]), "+f"(c[2]), "+f"(c[3])
        : "r"(a[0]), "r"(a[1]), "r"(a[2]), "r"(a[3]), "r"(b[0]), "r"(b[1]));
}
__device__ __forceinline__ void mma_tf32(float c[4], const uint32_t a[4], const uint32_t b[2]) {
    asm volatile(
        "mma.sync.aligned.m16n8k8.row.col.f32.tf32.tf32.f32 "
        "{%0,%1,%2,%3}, {%4,%5,%6,%7}, {%8,%9}, {%0,%1,%2,%3};"
        : "+f"(c[0]), "+f"(c[1]), "+f"(c[2]), "+f"(c[3])
        : "r"(a[0]), "r"(a[1]), "r"(a[2]), "r"(a[3]), "r"(b[0]), "r"(b[1]));
}
__device__ __forceinline__ void ldsm_x4(uint32_t& r0, uint32_t& r1, uint32_t& r2, uint32_t& r3,
                                        uint32_t addr) {
    asm volatile("ldmatrix.sync.aligned.m8n8.x4.shared.b16 {%0,%1,%2,%3}, [%4];"
                 : "=r"(r0), "=r"(r1), "=r"(r2), "=r"(r3) : "r"(addr));
}
__device__ __forceinline__ uint32_t tf32_of(float x) {
    uint32_t r;
    asm("cvt.rna.tf32.f32 %0, %1;" : "=r"(r) : "f"(x));
    return r;
}
#define CP_ASYNC16(dst, src) \
    asm volatile("cp.async.cg.shared.global [%0], [%1], 16;" :: "r"(dst), "l"(src))
#define CP_ASYNC8(dst, src) \
    asm volatile("cp.async.ca.shared.global [%0], [%1], 8;" :: "r"(dst), "l"(src))
#define CP_COMMIT() asm volatile("cp.async.commit_group;" ::: "memory")
#define CP_WAIT1()  asm volatile("cp.async.wait_group 1;" ::: "memory")
#define CP_WAIT0()  asm volatile("cp.async.wait_group 0;" ::: "memory")

// ---------------- kernel 1: pack adjacency + echo adj to output ----------------
__global__ void pack_adj_kernel(const int* __restrict__ adj,
                                float* __restrict__ outf, long out_size) {
    int gtid = blockIdx.x * blockDim.x + threadIdx.x;
    int warp = gtid >> 5, lane = gtid & 31;
    int row = warp / NW, wj = warp % NW;
    int j = wj * 32 + lane;
    int v = 0;
    if (j < N_NODES) {
        long idx = (long)row * N_NODES + j;
        v = adj[idx];
        long oi = (long)OUT_ADJ_OFF + idx;
        if (oi < out_size) outf[oi] = (float)v;
    }
    unsigned bits = __ballot_sync(0xFFFFFFFFu, v != 0);
    if (lane == 0) g_adjb[row * NW + wj] = bits;
}

// ---------------- tf32 GEMM + fused score epilogue (256 threads) ----------------
// Register-prefetch pipelined mainloop: next K-stage's A/B are loaded into
// registers while the current stage computes, hiding global-load latency.
template<int NB>
__device__ __forceinline__ void gemm_tf32_body(
    const float* __restrict__ Asrc,
    const float* __restrict__ Bsrc,
    __half* __restrict__ CtT,
    int i0,
    const float* __restrict__ a_src,
    const float* __restrict__ a_tgt,
    float* __restrict__ Ev, float* __restrict__ Fv,
    uint2* __restrict__ pkv)
{
    __shared__ __align__(16) char sbuf[17408];
    float* As = (float*)sbuf;                 // [128][20]
    float* Bs = (float*)(sbuf + 10240);       // [16][72]
    __half* T = (__half*)sbuf;                // [64][136] reused after mainloop

    int tid = threadIdx.x;
    int lane = tid & 31, warp = tid >> 5;
    int wr = warp >> 1, wc = warp & 1;

    float acc[2][4][4];
    #pragma unroll
    for (int m = 0; m < 2; m++)
        #pragma unroll
        for (int n = 0; n < 4; n++)
            #pragma unroll
            for (int c = 0; c < 4; c++) acc[m][n][c] = 0.f;

    int sr = tid >> 1, skk = (tid & 1) * 8;
    int bkk = tid >> 4, bn0 = (tid & 15) * 4;
    bool arow_ok = (i0 + sr) < N_NODES;
    const float* a_base = &Asrc[(size_t)(i0 + sr) * F_IN + skk];

    // prefetch k0 = 0
    float4 pa0 = make_float4(0.f, 0.f, 0.f, 0.f), pa1 = pa0, pb = pa0;
    if (arow_ok) {
        pa0 = *(const float4*)(a_base);
        pa1 = *(const float4*)(a_base + 4);
    }
    if (bn0 < NB)
        pb = *(const float4*)&Bsrc[(size_t)bkk * NB + bn0];

    for (int k0 = 0; k0 < F_IN; k0 += 16) {
        // store current stage (tf32 convert at STS)
        {
            uint32_t* d = (uint32_t*)&As[sr * 20 + skk];
            d[0] = tf32_of(pa0.x); d[1] = tf32_of(pa0.y); d[2] = tf32_of(pa0.z); d[3] = tf32_of(pa0.w);
            d[4] = tf32_of(pa1.x); d[5] = tf32_of(pa1.y); d[6] = tf32_of(pa1.z); d[7] = tf32_of(pa1.w);
            uint32_t* db = (uint32_t*)&Bs[bkk * 72 + bn0];
            db[0] = tf32_of(pb.x); db[1] = tf32_of(pb.y); db[2] = tf32_of(pb.z); db[3] = tf32_of(pb.w);
        }
        __syncthreads();

        // prefetch next stage into registers (latency overlapped with mma below)
        if (k0 + 16 < F_IN) {
            pa0 = make_float4(0.f, 0.f, 0.f, 0.f); pa1 = pa0; pb = pa0;
            if (arow_ok) {
                pa0 = *(const float4*)(a_base + k0 + 16);
                pa1 = *(const float4*)(a_base + k0 + 20);
            }
            if (bn0 < NB)
                pb = *(const float4*)&Bsrc[(size_t)(k0 + 16 + bkk) * NB + bn0];
        }

        #pragma unroll
        for (int s = 0; s < 2; s++) {
            int arow = wr * 32 + (lane >> 2);
            int akol = s * 8 + (lane & 3);
            uint32_t af[2][4];
            #pragma unroll
            for (int m = 0; m < 2; m++) {
                int base = (arow + m * 16) * 20 + akol;
                af[m][0] = __float_as_uint(As[base]);
                af[m][1] = __float_as_uint(As[base + 8 * 20]);
                af[m][2] = __float_as_uint(As[base + 4]);
                af[m][3] = __float_as_uint(As[base + 8 * 20 + 4]);
            }
            int bb = (s * 8 + (lane & 3)) * 72 + wc * 32 + (lane >> 2);
            uint32_t bf[4][2];
            #pragma unroll
            for (int n = 0; n < 4; n++) {
                bf[n][0] = __float_as_uint(Bs[bb + n * 8]);
                bf[n][1] = __float_as_uint(Bs[bb + n * 8 + 4 * 72]);
            }
            #pragma unroll
            for (int m = 0; m < 2; m++)
                #pragma unroll
                for (int n = 0; n < 4; n++)
                    mma_tf32(acc[m][n], af[m], bf[n]);
        }
        __syncthreads();
    }

    // fp16 transpose into smem
    int rl = wr * 32 + (lane >> 2);
    int cbx = wc * 32 + (lane & 3) * 2;
    #pragma unroll
    for (int m = 0; m < 2; m++) {
        int r0 = rl + m * 16, r1 = r0 + 8;
        #pragma unroll
        for (int n = 0; n < 4; n++) {
            int c = cbx + n * 8;
            T[(c + 0) * 136 + r0] = __float2half_rn(acc[m][n][0]);
            T[(c + 1) * 136 + r0] = __float2half_rn(acc[m][n][1]);
            T[(c + 0) * 136 + r1] = __float2half_rn(acc[m][n][2]);
            T[(c + 1) * 136 + r1] = __float2half_rn(acc[m][n][3]);
        }
    }
    __syncthreads();

    // global fp16 transposed writeback
    #pragma unroll
    for (int q = 0; q < 4; q++) {
        int l = tid + 256 * q;               // 0..1023
        int d = l >> 4, o = (l & 15) * 8;
        *(uint4*)&CtT[(size_t)d * JP + i0 + o] = *(uint4*)&T[d * 136 + o];
    }

    // ---- fused scores: 2 threads per row, each sums 32 cols from T ----
    {
        int row_l = tid >> 1, hv = tid & 1;
        float ss = 0.f, st = 0.f;
        #pragma unroll 8
        for (int c = hv * 32; c < hv * 32 + 32; c++) {
            if (c < NB) {
                float w = __half2float(T[c * 136 + row_l]);
                ss += w * __ldg(&a_src[c]);
                st += w * __ldg(&a_tgt[c]);
            }
        }
        ss += __shfl_xor_sync(0xFFFFFFFFu, ss, 1);
        st += __shfl_xor_sync(0xFFFFFFFFu, st, 1);
        int row_g = i0 + row_l;
        if (hv == 0 && row_g < N_NODES) {
            Ev[row_g] = expf(ss);
            Fv[row_g] = expf(ALPHA * ss);
            __half* pw = (__half*)&pkv[row_g >> 1];
            int o = row_g & 1;
            pw[0 + o] = __float2half_rn(expf(st));
            pw[2 + o] = __float2half_rn(expf(ALPHA * st));
        }
    }
}

__global__ void __launch_bounds__(256) gemm1_kernel(const float* __restrict__ x,
                                                    const float* __restrict__ W1,
                                                    const float* __restrict__ a_src,
                                                    const float* __restrict__ a_tgt) {
    int h = blockIdx.y;
    gemm_tf32_body<HID>(x, W1 + (size_t)h * F_IN * HID,
                        g_WhT + (size_t)h * HID * JP,
                        blockIdx.x * 128,
                        a_src + h * HID, a_tgt + h * HID,
                        g_Ei + h * N_NODES, g_Fi + h * N_NODES,
                        g_pk1 + (size_t)h * (JP / 2));
}

__global__ void __launch_bounds__(256) gemm2_kernel(const float* __restrict__ W2,
                                                    const float* __restrict__ a_src2,
                                                    const float* __restrict__ a_tgt2) {
    gemm_tf32_body<C_OUT>(g_h1, W2, g_WhT2, blockIdx.x * 128,
                          a_src2, a_tgt2, g_E2i, g_F2i, g_pk2);
}

// ---------------- fused masked-softmax AV on mma.sync ----------------
// 128 threads = 4 warps, 32 rows/warp (2 row-groups) -> 128 rows/block.
// w = mask * max(Ei*ej, Fi*fj). Adjacency + scalars through cp.async pipeline.
template<int NG, int NGL, bool L2K>
__global__ void __launch_bounds__(128, 4) av_mma_kernel(float* __restrict__ dummy) {
    __shared__ __align__(16) __half Bbuf[3][64 * 72];
    __shared__ __align__(16) uint2  Pbuf[3][32];
    __shared__ __align__(16) uint2  Abuf[3][128];

    int tid = threadIdx.x;
    int lane = tid & 31, warp = tid >> 5;
    int i0 = blockIdx.x * 128;

    const float *Eiv, *Fiv;
    const uint2* pk;
    const __half* whT;
    int tbeg, NT, pidx, zcol;
    if (L2K) {
        Eiv = g_E2i; Fiv = g_F2i;
        pk = g_pk2; whT = g_WhT2;
        int y = blockIdx.y;                    // 12-way split: 10x8 + 2x7 = 94
        tbeg = (y < 10) ? y * 8 : 80 + (y - 10) * 7;
        NT   = (y < 10) ? 8 : 7;
        pidx = y; zcol = 40;
    } else {
        int h = blockIdx.y;
        int hb = h * N_NODES;
        Eiv = g_Ei + hb; Fiv = g_Fi + hb;
        pk = g_pk1 + (size_t)h * (JP / 2);
        whT = g_WhT + (size_t)h * HID * JP;
        int z = blockIdx.z;                    // 3-way j split: 32,31,31
        tbeg = (z == 0) ? 0 : 32 + (z - 1) * 31;
        NT   = (z == 0) ? 32 : 31;
        pidx = h * 3 + z; zcol = 64;
    }

    // 4 row slots: r0 + {0,8,16,24}
    int r0 = i0 + warp * 32 + (lane >> 2);
    __half2 E2[4], F2[4];
    #pragma unroll
    for (int s = 0; s < 4; s++) {
        int rc = min(r0 + s * 8, N_NODES - 1);
        E2[s] = __half2half2(__float2half_rn(Eiv[rc]));
        F2[s] = __half2half2(__float2half_rn(Fiv[rc]));
    }
    int c4 = lane & 3, cb = c4 * 2;

    const unsigned* adj_mine = &g_adjb[(size_t)min(i0 + tid, N_NODES - 1) * NW];
    int aidx = warp * 32 + (lane >> 2);

    int nb = (lane & 7) | (((lane >> 4) & 1) << 3);
    int kb = ((lane >> 3) & 1) * 8;
    uint32_t bB[3] = { smem_u32(Bbuf[0]), smem_u32(Bbuf[1]), smem_u32(Bbuf[2]) };
    uint32_t lds_off = (uint32_t)(nb * 72 + kb) * 2;

    float acc[2][NG][4];
    float accz[2][4];
    #pragma unroll
    for (int g = 0; g < 2; g++) {
        #pragma unroll
        for (int n = 0; n < NG; n++)
            #pragma unroll
            for (int c = 0; c < 4; c++) acc[g][n][c] = 0.f;
        #pragma unroll
        for (int c = 0; c < 4; c++) accz[g][c] = 0.f;
    }

    const uint32_t ONES2 = 0x3C003C00u;
    const uint32_t bz[2] = { ONES2, ONES2 };

    auto stage = [&](int t, int b) {
        int j0 = (tbeg + t) * 64;
        #pragma unroll
        for (int i2 = 0; i2 < 4; i2++) {
            int c = tid + 128 * i2;
            int n = c >> 3, o = c & 7;
            CP_ASYNC16(bB[b] + (uint32_t)(n * 144 + o * 16),
                       whT + (size_t)n * JP + j0 + o * 8);
        }
        CP_ASYNC8(smem_u32(&Abuf[b][tid]), adj_mine + 2 * (tbeg + t));
        if (tid >= 96 && tid < 112) {
            int e = tid - 96;
            CP_ASYNC16(smem_u32(&Pbuf[b][e * 2]), pk + (j0 >> 1) + e * 2);
        }
    };

    stage(0, 0); CP_COMMIT();
    if (NT > 1) { stage(1, 1); CP_COMMIT(); }

    for (int t = 0; t < NT; t++) {
        int b = t % 3;
        if (t + 1 < NT) CP_WAIT1(); else CP_WAIT0();
        __syncthreads();
        if (t + 2 < NT) { stage(t + 2, (t + 2) % 3); CP_COMMIT(); }

        uint2 aw[4];
        #pragma unroll
        for (int s = 0; s < 4; s++)
            aw[s] = Abuf[b][aidx + s * 8];

        #pragma unroll
        for (int ks = 0; ks < 4; ks++) {
            uint2 p0 = Pbuf[b][ks * 8 + c4];
            uint2 p1 = Pbuf[b][ks * 8 + c4 + 4];
            __half2 eA = *(__half2*)&p0.x, fA = *(__half2*)&p0.y;
            __half2 eB = *(__half2*)&p1.x, fB = *(__half2*)&p1.y;

            int sh = ((ks & 1) << 4) + cb;
            uint32_t a2[2][4];
            #pragma unroll
            for (int g = 0; g < 2; g++) {
                #pragma unroll
                for (int rr = 0; rr < 2; rr++) {
                    int s = g * 2 + rr;
                    unsigned word = (ks < 2) ? aw[s].x : aw[s].y;
                    unsigned ta = word >> sh;
                    unsigned tb2 = ta >> 8;
                    uint32_t ma = (ta  & 1u) * 0x3C00u + (ta  & 2u) * 0x1E000000u;
                    uint32_t mb = (tb2 & 1u) * 0x3C00u + (tb2 & 2u) * 0x1E000000u;

                    __half2 wa = __hmul2(
                        __hmax2(__hmul2(E2[s], eA), __hmul2(F2[s], fA)), *(__half2*)&ma);
                    __half2 wbv = __hmul2(
                        __hmax2(__hmul2(E2[s], eB), __hmul2(F2[s], fB)), *(__half2*)&mb);

                    a2[g][rr]     = *(uint32_t*)&wa;
                    a2[g][rr + 2] = *(uint32_t*)&wbv;
                }
            }
            #pragma unroll
            for (int p = 0; p < NGL / 2; p++) {
                uint32_t bf0[2], bf1[2];
                ldsm_x4(bf0[0], bf0[1], bf1[0], bf1[1],
                        bB[b] + lds_off + (uint32_t)(p * 16 * 144 + ks * 32));
                int n0 = 2 * p, n1 = 2 * p + 1;
                if (n0 < NG) { mma_16816(acc[0][n0], a2[0], bf0); mma_16816(acc[1][n0], a2[1], bf0); }
                if (n1 < NG) { mma_16816(acc[0][n1], a2[0], bf1); mma_16816(acc[1][n1], a2[1], bf1); }
            }
            mma_16816(accz[0], a2[0], bz);
            mma_16816(accz[1], a2[1], bz);
        }
    }

    // ---- epilogue: partial store (D cols + Z) ----
    #pragma unroll
    for (int g = 0; g < 2; g++) {
        #pragma unroll
        for (int rr = 0; rr < 2; rr++) {
            int row = r0 + (g * 2 + rr) * 8;
            if (row >= N_NODES) continue;
            size_t base = ((size_t)pidx * 6016 + row) * 72;
            #pragma unroll
            for (int n = 0; n < NG; n++)
                *(float2*)&g_part[base + n * 8 + cb] =
                    make_float2(acc[g][n][rr * 2], acc[g][n][rr * 2 + 1]);
            if (cb == 0) g_part[base + zcol] = accz[g][rr * 2];
        }
    }
}

// ---------------- layer-1 combine (3 parts per head): normalize + ELU -> g_h1 ----------------
__global__ void combine1_kernel() {
    int idx = blockIdx.x * blockDim.x + threadIdx.x;
    if (idx >= H1 * N_NODES * 32) return;
    int c2 = idx & 31;
    int rest = idx >> 5;
    int row = rest % N_NODES;
    int h = rest / N_NODES;
    float na = 0.f, nb2 = 0.f, z = 0.f;
    #pragma unroll
    for (int k = 0; k < 3; k++) {
        size_t b = ((size_t)(h * 3 + k) * 6016 + row) * 72;
        float2 v = *(float2*)&g_part[b + c2 * 2];
        na += v.x; nb2 += v.y;
        z += g_part[b + 64];
    }
    float invZ = 1.0f / z;
    float a = na * invZ, b = nb2 * invZ;
    a = a > 0.f ? a : expm1f(a);
    b = b > 0.f ? b : expm1f(b);
    *(float2*)&g_h1[(size_t)row * (H1 * HID) + h * HID + c2 * 2] = make_float2(a, b);
}

// ---------------- layer-2 partial combine (12 parts) ----------------
__global__ void combine2_kernel(float* __restrict__ out) {
    int idx = blockIdx.x * blockDim.x + threadIdx.x;
    if (idx >= N_NODES * C_OUT) return;
    int row = idx / C_OUT, c = idx - row * C_OUT;
    float num = 0.f, z = 0.f;
    #pragma unroll
    for (int y = 0; y < 12; y++) {
        size_t b = ((size_t)y * 6016 + row) * 72;
        num += g_part[b + c];
        z   += g_part[b + 40];
    }
    out[idx] = num / z;
}

// ---------------- launch ----------------
extern "C" void kernel_launch(void* const* d_in, const int* in_sizes, int n_in,
                              void* d_out, int out_size) {
    const float* x      = (const float*)d_in[0];
    const int*   adj    = (const int*)  d_in[1];
    const float* W1     = (const float*)d_in[2];
    const float* a_src1 = (const float*)d_in[3];
    const float* a_tgt1 = (const float*)d_in[4];
    const float* W2     = (const float*)d_in[5];
    const float* a_src2 = (const float*)d_in[6];
    const float* a_tgt2 = (const float*)d_in[7];
    float* out = (float*)d_out;

    pack_adj_kernel<<<(N_NODES * NW * 32) / 256, 256>>>(adj, out, (long)out_size);

    gemm1_kernel<<<dim3((N_NODES + 127) / 128, H1), 256>>>(x, W1, a_src1, a_tgt1);
    av_mma_kernel<8, 8, false><<<dim3(JP / 128, H1, 3), 128>>>(nullptr);
    combine1_kernel<<<(H1 * N_NODES * 32 + 255) / 256, 256>>>();

    gemm2_kernel<<<(N_NODES + 127) / 128, 256>>>(W2, a_src2, a_tgt2);
    av_mma_kernel<5, 6, true><<<dim3(JP / 128, 12), 128>>>(nullptr);
    combine2_kernel<<<(N_NODES * C_OUT + 255) / 256, 256>>>(out);
}